// round 1
// baseline (speedup 1.0000x reference)
#include <cuda_runtime.h>
#include <math.h>
#include <stdint.h>

#define EMBED   1024
#define HEADS   16
#define HDIM    64
#define BATCH   4
#define TSEQ    2048
#define MROWS   (BATCH * TSEQ)   // 8192

// -------- scratch (no cudaMalloc allowed) --------
__device__ float g_q[BATCH * HEADS * TSEQ * HDIM];   // (B,H,T,D)
__device__ float g_k[BATCH * HEADS * TSEQ * HDIM];
__device__ float g_v[BATCH * HEADS * TSEQ * HDIM];
__device__ float g_o[BATCH * TSEQ * EMBED];          // (B,T,C)

// ============================================================
// SGEMM: C[M,N] = A[M,K] @ W[K,N] + bias
// M=8192, N=K=1024. BM=BN=128, BK=8, TM=TN=8, 256 threads.
// SPLIT: scatter output into (B,H,T,D) head-split layout.
// ============================================================
template<bool SPLIT>
__global__ __launch_bounds__(256)
void sgemm_kernel(const float* __restrict__ A,
                  const float* __restrict__ W,
                  const float* __restrict__ bias,
                  float* __restrict__ C)
{
    constexpr int N = EMBED, K = EMBED;

    __shared__ float As[8][128];   // transposed A tile
    __shared__ float Bs[8][128];

    const int tid = threadIdx.x;
    const int bx = blockIdx.x;     // N tile
    const int by = blockIdx.y;     // M tile
    const int tx = tid & 15;       // 0..15
    const int ty = tid >> 4;       // 0..15

    const int arow = tid >> 1;         // 0..127
    const int acol = (tid & 1) * 4;    // 0 or 4
    const int brow = tid >> 5;         // 0..7
    const int bcol = (tid & 31) * 4;   // 0..124

    const float* Aptr = A + (size_t)(by * 128 + arow) * K + acol;
    const float* Bptr = W + (size_t)brow * N + bx * 128 + bcol;

    float acc[8][8];
    #pragma unroll
    for (int i = 0; i < 8; i++)
        #pragma unroll
        for (int j = 0; j < 8; j++) acc[i][j] = 0.f;

    for (int kt = 0; kt < K; kt += 8) {
        float4 av = *(const float4*)(Aptr + kt);
        As[acol + 0][arow] = av.x;
        As[acol + 1][arow] = av.y;
        As[acol + 2][arow] = av.z;
        As[acol + 3][arow] = av.w;
        *(float4*)(&Bs[brow][bcol]) = *(const float4*)(Bptr + (size_t)kt * N);
        __syncthreads();

        #pragma unroll
        for (int k = 0; k < 8; k++) {
            float4 a0 = *(const float4*)(&As[k][ty * 8]);
            float4 a1 = *(const float4*)(&As[k][ty * 8 + 4]);
            float4 b0 = *(const float4*)(&Bs[k][tx * 8]);
            float4 b1 = *(const float4*)(&Bs[k][tx * 8 + 4]);
            float ra[8] = {a0.x, a0.y, a0.z, a0.w, a1.x, a1.y, a1.z, a1.w};
            float rb[8] = {b0.x, b0.y, b0.z, b0.w, b1.x, b1.y, b1.z, b1.w};
            #pragma unroll
            for (int i = 0; i < 8; i++)
                #pragma unroll
                for (int j = 0; j < 8; j++)
                    acc[i][j] += ra[i] * rb[j];
        }
        __syncthreads();
    }

    #pragma unroll
    for (int i = 0; i < 8; i++) {
        const int m = by * 128 + ty * 8 + i;
        #pragma unroll
        for (int j = 0; j < 8; j++) {
            const int n = bx * 128 + tx * 8 + j;
            const float v = acc[i][j] + bias[n];
            if (SPLIT) {
                const int b = m / TSEQ, t = m % TSEQ;
                const int h = n >> 6, d = n & 63;
                C[(((size_t)(b * HEADS + h)) * TSEQ + t) * HDIM + d] = v;
            } else {
                C[(size_t)m * N + n] = v;
            }
        }
    }
}

// ============================================================
// Causal flash attention, fp32.
// Grid: (T/64, B*H). 256 threads = 8 warps.
// Warp w owns query rows w*8..w*8+7 of a 64-row Q tile.
// Lane owns keys {lane, lane+32} of the 64-key K tile (scores)
// and output dims {lane, lane+32} (PV).
// ============================================================
__global__ __launch_bounds__(256)
void attn_kernel(const float* __restrict__ Q,
                 const float* __restrict__ K,
                 const float* __restrict__ V,
                 float* __restrict__ O)
{
    extern __shared__ float sm[];
    float* Qs = sm;                // [64][64]
    float* Ks = Qs + 64 * 64;      // [64][65] padded
    float* Vs = Ks + 64 * 65;      // [64][64]
    float* Ps = Vs + 64 * 64;      // [64][64]

    const int qt   = blockIdx.x;   // 0..31
    const int bh   = blockIdx.y;   // 0..63
    const int tid  = threadIdx.x;
    const int w    = tid >> 5;
    const int lane = tid & 31;
    const int q0   = qt * 64;

    // ---- load Q tile (contiguous 4096 floats) ----
    {
        const float4* src = (const float4*)(Q + ((size_t)bh * TSEQ + q0) * HDIM);
        float4* dst = (float4*)Qs;
        #pragma unroll
        for (int i = tid; i < 1024; i += 256) dst[i] = src[i];
    }

    float m[8], l[8], acc0[8], acc1[8];
    #pragma unroll
    for (int rr = 0; rr < 8; rr++) {
        m[rr] = -INFINITY; l[rr] = 0.f; acc0[rr] = 0.f; acc1[rr] = 0.f;
    }

    const int ntiles = qt + 1;
    for (int ktile = 0; ktile < ntiles; ktile++) {
        const int k0 = ktile * 64;
        __syncthreads();   // prior-iter consumers done (also guards Q load, 1st iter)

        const float* kbase = K + ((size_t)bh * TSEQ + k0) * HDIM;
        const float* vbase = V + ((size_t)bh * TSEQ + k0) * HDIM;
        #pragma unroll
        for (int i = tid; i < 4096; i += 256) {
            const int r = i >> 6, c = i & 63;
            Ks[r * 65 + c] = kbase[i];
            Vs[r * 64 + c] = vbase[i];
        }
        __syncthreads();

        // ---- scores: 8 rows x 2 keys per lane ----
        float sc0[8], sc1[8];
        #pragma unroll
        for (int rr = 0; rr < 8; rr++) { sc0[rr] = 0.f; sc1[rr] = 0.f; }
        #pragma unroll
        for (int d = 0; d < 64; d++) {
            const float kv0 = Ks[lane * 65 + d];
            const float kv1 = Ks[(lane + 32) * 65 + d];
            #pragma unroll
            for (int rr = 0; rr < 8; rr++) {
                const float qv = Qs[(w * 8 + rr) * 64 + d];
                sc0[rr] += qv * kv0;
                sc1[rr] += qv * kv1;
            }
        }

        // ---- causal mask + online softmax per row ----
        #pragma unroll
        for (int rr = 0; rr < 8; rr++) {
            const int qi = q0 + w * 8 + rr;
            float s0 = (k0 + lane      <= qi) ? sc0[rr] * 0.125f : -INFINITY;
            float s1 = (k0 + lane + 32 <= qi) ? sc1[rr] * 0.125f : -INFINITY;
            float tmax = fmaxf(s0, s1);
            #pragma unroll
            for (int off = 16; off > 0; off >>= 1)
                tmax = fmaxf(tmax, __shfl_xor_sync(0xffffffffu, tmax, off));
            const float nm = fmaxf(m[rr], tmax);
            const float scale = __expf(m[rr] - nm);
            const float p0 = __expf(s0 - nm);
            const float p1 = __expf(s1 - nm);
            float ps = p0 + p1;
            #pragma unroll
            for (int off = 16; off > 0; off >>= 1)
                ps += __shfl_xor_sync(0xffffffffu, ps, off);
            l[rr] = l[rr] * scale + ps;
            m[rr] = nm;
            acc0[rr] *= scale;
            acc1[rr] *= scale;
            Ps[(w * 8 + rr) * 64 + lane]      = p0;
            Ps[(w * 8 + rr) * 64 + lane + 32] = p1;
        }
        __syncwarp();   // Ps rows are warp-private: warp-level sync suffices

        // ---- PV: out dims {lane, lane+32} ----
        #pragma unroll 4
        for (int k = 0; k < 64; k++) {
            const float v0 = Vs[k * 64 + lane];
            const float v1 = Vs[k * 64 + lane + 32];
            #pragma unroll
            for (int rr = 0; rr < 8; rr++) {
                const float p = Ps[(w * 8 + rr) * 64 + k];
                acc0[rr] += p * v0;
                acc1[rr] += p * v1;
            }
        }
    }

    // ---- write (B,T,C) ----
    const int b = bh >> 4, h = bh & 15;
    #pragma unroll
    for (int rr = 0; rr < 8; rr++) {
        const float inv = 1.0f / l[rr];
        const int t = q0 + w * 8 + rr;
        float* op = O + ((size_t)(b * TSEQ + t)) * EMBED + h * HDIM;
        op[lane]      = acc0[rr] * inv;
        op[lane + 32] = acc1[rr] * inv;
    }
}

// ============================================================
extern "C" void kernel_launch(void* const* d_in, const int* in_sizes, int n_in,
                              void* d_out, int out_size)
{
    const float* x  = (const float*)d_in[0];
    const float* Wq = (const float*)d_in[1];
    const float* bq = (const float*)d_in[2];
    const float* Wk = (const float*)d_in[3];
    const float* bk = (const float*)d_in[4];
    const float* Wv = (const float*)d_in[5];
    const float* bv = (const float*)d_in[6];
    const float* Wp = (const float*)d_in[7];
    const float* bp = (const float*)d_in[8];
    float* out = (float*)d_out;

    float *q, *k, *v, *o;
    cudaGetSymbolAddress((void**)&q, g_q);
    cudaGetSymbolAddress((void**)&k, g_k);
    cudaGetSymbolAddress((void**)&v, g_v);
    cudaGetSymbolAddress((void**)&o, g_o);

    const int attn_smem = (64 * 64 + 64 * 65 + 64 * 64 + 64 * 64) * (int)sizeof(float);
    cudaFuncSetAttribute(attn_kernel, cudaFuncAttributeMaxDynamicSharedMemorySize, attn_smem);

    dim3 gemm_grid(EMBED / 128, MROWS / 128);   // (8, 64)
    sgemm_kernel<true ><<<gemm_grid, 256>>>(x, Wq, bq, q);
    sgemm_kernel<true ><<<gemm_grid, 256>>>(x, Wk, bk, k);
    sgemm_kernel<true ><<<gemm_grid, 256>>>(x, Wv, bv, v);

    dim3 attn_grid(TSEQ / 64, BATCH * HEADS);   // (32, 64)
    attn_kernel<<<attn_grid, 256, attn_smem>>>(q, k, v, o);

    sgemm_kernel<false><<<gemm_grid, 256>>>(o, Wp, bp, out);
    (void)in_sizes; (void)n_in; (void)out_size;
}

// round 3
// speedup vs baseline: 1.9515x; 1.9515x over previous
#include <cuda_runtime.h>
#include <cuda_bf16.h>
#include <math.h>
#include <stdint.h>

#define EMBED   1024
#define HEADS   16
#define HDIM    64
#define BATCH   4
#define TSEQ    2048
#define MROWS   (BATCH * TSEQ)   // 8192

// ================= helpers =================
__device__ __forceinline__ uint32_t smem_u32(const void* p) {
    uint32_t a;
    asm("{ .reg .u64 t; cvta.to.shared.u64 t, %1; cvt.u32.u64 %0, t; }" : "=r"(a) : "l"(p));
    return a;
}
__device__ __forceinline__ uint32_t swz128(uint32_t off) { return off ^ ((off >> 3) & 0x70); }

__device__ __forceinline__ void cp_async16(uint32_t dst, const void* src) {
    asm volatile("cp.async.cg.shared.global [%0], [%1], 16;" :: "r"(dst), "l"(src));
}
#define CP_COMMIT() asm volatile("cp.async.commit_group;" ::: "memory")
#define CP_WAIT(n)  asm volatile("cp.async.wait_group %0;" :: "n"(n) : "memory")

__device__ __forceinline__ void ldsm_x4(uint32_t* r, uint32_t addr) {
    asm volatile("ldmatrix.sync.aligned.m8n8.x4.shared.b16 {%0,%1,%2,%3}, [%4];"
        : "=r"(r[0]), "=r"(r[1]), "=r"(r[2]), "=r"(r[3]) : "r"(addr));
}
__device__ __forceinline__ void mma16816(float* d, const uint32_t* a, const uint32_t* b) {
    asm volatile("mma.sync.aligned.m16n8k16.row.col.f32.bf16.bf16.f32 "
        "{%0,%1,%2,%3}, {%4,%5,%6,%7}, {%8,%9}, {%0,%1,%2,%3};"
        : "+f"(d[0]), "+f"(d[1]), "+f"(d[2]), "+f"(d[3])
        : "r"(a[0]), "r"(a[1]), "r"(a[2]), "r"(a[3]), "r"(b[0]), "r"(b[1]));
}

// ================= scratch =================
__device__ float g_q[BATCH * HEADS * TSEQ * HDIM];
__device__ float g_k[BATCH * HEADS * TSEQ * HDIM];
__device__ float g_v[BATCH * HEADS * TSEQ * HDIM];
__device__ float g_o[BATCH * TSEQ * EMBED];
__device__ __nv_bfloat16 g_xhi[MROWS * EMBED];
__device__ __nv_bfloat16 g_xlo[MROWS * EMBED];
__device__ __nv_bfloat16 g_ohi[MROWS * EMBED];
__device__ __nv_bfloat16 g_olo[MROWS * EMBED];
__device__ __nv_bfloat16 g_wthi[4 * EMBED * EMBED];   // Wt[N,K] per weight
__device__ __nv_bfloat16 g_wtlo[4 * EMBED * EMBED];

// ================= split conversion (A-side) =================
__global__ __launch_bounds__(256)
void split_f32(const float* __restrict__ in, __nv_bfloat16* __restrict__ hi,
               __nv_bfloat16* __restrict__ lo, int n4)
{
    int i = blockIdx.x * blockDim.x + threadIdx.x;
    if (i >= n4) return;
    float4 v = ((const float4*)in)[i];
    __nv_bfloat16 h[4], l[4];
    float f[4] = {v.x, v.y, v.z, v.w};
    #pragma unroll
    for (int j = 0; j < 4; j++) {
        h[j] = __float2bfloat16(f[j]);
        l[j] = __float2bfloat16(f[j] - __bfloat162float(h[j]));
    }
    ((ushort4*)hi)[i] = make_ushort4(__bfloat16_as_ushort(h[0]), __bfloat16_as_ushort(h[1]),
                                     __bfloat16_as_ushort(h[2]), __bfloat16_as_ushort(h[3]));
    ((ushort4*)lo)[i] = make_ushort4(__bfloat16_as_ushort(l[0]), __bfloat16_as_ushort(l[1]),
                                     __bfloat16_as_ushort(l[2]), __bfloat16_as_ushort(l[3]));
}

// ================= transpose + split (W[K,N] -> Wt[N,K] hi/lo) =================
__global__ __launch_bounds__(256)
void transpose_split(const float* __restrict__ W, __nv_bfloat16* __restrict__ hi,
                     __nv_bfloat16* __restrict__ lo)
{
    __shared__ float t[32][33];
    const int bx = blockIdx.x * 32;   // N
    const int by = blockIdx.y * 32;   // K
    const int x = threadIdx.x, y = threadIdx.y;  // 32 x 8
    #pragma unroll
    for (int j = 0; j < 32; j += 8)
        t[y + j][x] = W[(size_t)(by + y + j) * EMBED + bx + x];
    __syncthreads();
    #pragma unroll
    for (int j = 0; j < 32; j += 8) {
        float v = t[x][y + j];
        __nv_bfloat16 h = __float2bfloat16(v);
        __nv_bfloat16 l = __float2bfloat16(v - __bfloat162float(h));
        size_t idx = (size_t)(bx + y + j) * EMBED + by + x;
        hi[idx] = h;
        lo[idx] = l;
    }
}

// ================= HMMA bf16x3 GEMM =================
// C[128,128] tile: C = A[M,K] * Wt[N,K]^T + bias. bf16x3: AhiBhi + AhiBlo + AloBhi.
// 8 warps: warp_m = wid&3 (32 rows), warp_n = wid>>2 (64 cols).
template<bool SPLIT>
__global__ __launch_bounds__(256)
void mma_gemm(const __nv_bfloat16* __restrict__ Ahi, const __nv_bfloat16* __restrict__ Alo,
              const __nv_bfloat16* __restrict__ Bhi, const __nv_bfloat16* __restrict__ Blo,
              const float* __restrict__ bias, float* __restrict__ C)
{
    constexpr int K = EMBED, NG = EMBED;
    constexpr int BK = 64, NK = K / BK;      // 16 chunks
    constexpr int TILE_B = 128 * BK * 2;     // 16384 bytes per tile
    constexpr int STAGE_B = 4 * TILE_B;      // 65536
    extern __shared__ __align__(1024) char smem[];
    const uint32_t sb = smem_u32(smem);
    const int tid = threadIdx.x, wid = tid >> 5, lane = tid & 31;
    const int n0 = blockIdx.x * 128, m0 = blockIdx.y * 128;
    const int warp_m = wid & 3, warp_n = wid >> 2;

    const __nv_bfloat16* srcs[4] = {Ahi, Alo, Bhi, Blo};

    auto load_chunk = [&](int kt, int s) {
        #pragma unroll
        for (int t = 0; t < 4; t++) {
            const __nv_bfloat16* base = srcs[t] + (size_t)((t < 2) ? m0 : n0) * K + kt * BK;
            const uint32_t tb = sb + s * STAGE_B + t * TILE_B;
            #pragma unroll
            for (int i = 0; i < 4; i++) {
                int chunk = tid + i * 256;          // 0..1023
                int r = chunk >> 3, c = chunk & 7;  // row 0..127, 16B-chunk 0..7
                cp_async16(tb + swz128(r * 128 + c * 16), base + (size_t)r * K + c * 8);
            }
        }
        CP_COMMIT();
    };

    float acc[2][8][4];
    #pragma unroll
    for (int mb = 0; mb < 2; mb++)
        #pragma unroll
        for (int nb = 0; nb < 8; nb++)
            #pragma unroll
            for (int j = 0; j < 4; j++) acc[mb][nb][j] = 0.f;

    // fragment smem address pieces (within a tile)
    const int a_row = warp_m * 32 + (lane & 7) + ((lane >> 3) & 1) * 8;  // + mb*16
    const int a_col = (lane >> 4) * 16;                                  // + ks*32
    const int b_row = warp_n * 64 + (lane & 7) + (lane >> 4) * 8;        // + nb16*16
    const int b_col = ((lane >> 3) & 1) * 16;                            // + ks*32

    load_chunk(0, 0);
    for (int kt = 0; kt < NK; kt++) {
        const int cur = kt & 1;
        if (kt + 1 < NK) { load_chunk(kt + 1, cur ^ 1); CP_WAIT(1); }
        else             { CP_WAIT(0); }
        __syncthreads();

        const uint32_t tAh = sb + cur * STAGE_B + 0 * TILE_B;
        const uint32_t tAl = sb + cur * STAGE_B + 1 * TILE_B;
        const uint32_t tBh = sb + cur * STAGE_B + 2 * TILE_B;
        const uint32_t tBl = sb + cur * STAGE_B + 3 * TILE_B;

        #pragma unroll
        for (int ks = 0; ks < 4; ks++) {
            uint32_t ah[2][4], al[2][4], bh[4][4], bl[4][4];
            #pragma unroll
            for (int mb = 0; mb < 2; mb++) {
                const uint32_t off = swz128((a_row + mb * 16) * 128 + a_col + ks * 32);
                ldsm_x4(ah[mb], tAh + off);
                ldsm_x4(al[mb], tAl + off);
            }
            #pragma unroll
            for (int nb = 0; nb < 4; nb++) {
                const uint32_t off = swz128((b_row + nb * 16) * 128 + b_col + ks * 32);
                ldsm_x4(bh[nb], tBh + off);
                ldsm_x4(bl[nb], tBl + off);
            }
            #pragma unroll
            for (int mb = 0; mb < 2; mb++)
                #pragma unroll
                for (int nb = 0; nb < 4; nb++)
                    #pragma unroll
                    for (int h = 0; h < 2; h++) {
                        float* d = acc[mb][nb * 2 + h];
                        mma16816(d, ah[mb], &bh[nb][h * 2]);
                        mma16816(d, ah[mb], &bl[nb][h * 2]);
                        mma16816(d, al[mb], &bh[nb][h * 2]);
                    }
        }
        __syncthreads();
    }

    // epilogue: fragment (mb, nb): rows m0+warp_m*32+mb*16+lane/4 (+8), cols n0+warp_n*64+nb*8+(lane%4)*2 (+1)
    const int er = m0 + warp_m * 32 + (lane >> 2);
    const int ec = n0 + warp_n * 64 + (lane & 3) * 2;
    #pragma unroll
    for (int mb = 0; mb < 2; mb++) {
        #pragma unroll
        for (int half = 0; half < 2; half++) {
            const int row = er + mb * 16 + half * 8;
            #pragma unroll
            for (int nb = 0; nb < 8; nb++) {
                const int col = ec + nb * 8;
                const float v0 = acc[mb][nb][half * 2 + 0] + bias[col];
                const float v1 = acc[mb][nb][half * 2 + 1] + bias[col + 1];
                if (SPLIT) {
                    const int b = row / TSEQ, t = row % TSEQ;
                    const int hh = col >> 6, dd = col & 63;
                    float* p = &g_q[0];  // dummy to keep type; real base passed via C
                    (void)p;
                    float* dst = C + (((size_t)(b * HEADS + hh)) * TSEQ + t) * HDIM + dd;
                    dst[0] = v0;
                    dst[1] = v1;
                } else {
                    float* dst = C + (size_t)row * NG + col;
                    dst[0] = v0;
                    dst[1] = v1;
                }
            }
        }
    }
}

// ================= causal flash attention (fp32, unchanged) =================
__global__ __launch_bounds__(256)
void attn_kernel(const float* __restrict__ Q, const float* __restrict__ K,
                 const float* __restrict__ V, float* __restrict__ O)
{
    extern __shared__ float sm[];
    float* Qs = sm;
    float* Ks = Qs + 64 * 64;
    float* Vs = Ks + 64 * 65;
    float* Ps = Vs + 64 * 64;

    const int qt = blockIdx.x, bh = blockIdx.y;
    const int tid = threadIdx.x, w = tid >> 5, lane = tid & 31;
    const int q0 = qt * 64;

    {
        const float4* src = (const float4*)(Q + ((size_t)bh * TSEQ + q0) * HDIM);
        float4* dst = (float4*)Qs;
        #pragma unroll
        for (int i = tid; i < 1024; i += 256) dst[i] = src[i];
    }

    float m[8], l[8], acc0[8], acc1[8];
    #pragma unroll
    for (int rr = 0; rr < 8; rr++) { m[rr] = -INFINITY; l[rr] = 0.f; acc0[rr] = 0.f; acc1[rr] = 0.f; }

    const int ntiles = qt + 1;
    for (int ktile = 0; ktile < ntiles; ktile++) {
        const int k0 = ktile * 64;
        __syncthreads();
        const float* kbase = K + ((size_t)bh * TSEQ + k0) * HDIM;
        const float* vbase = V + ((size_t)bh * TSEQ + k0) * HDIM;
        #pragma unroll
        for (int i = tid; i < 4096; i += 256) {
            const int r = i >> 6, c = i & 63;
            Ks[r * 65 + c] = kbase[i];
            Vs[r * 64 + c] = vbase[i];
        }
        __syncthreads();

        float sc0[8], sc1[8];
        #pragma unroll
        for (int rr = 0; rr < 8; rr++) { sc0[rr] = 0.f; sc1[rr] = 0.f; }
        #pragma unroll
        for (int d = 0; d < 64; d++) {
            const float kv0 = Ks[lane * 65 + d];
            const float kv1 = Ks[(lane + 32) * 65 + d];
            #pragma unroll
            for (int rr = 0; rr < 8; rr++) {
                const float qv = Qs[(w * 8 + rr) * 64 + d];
                sc0[rr] += qv * kv0;
                sc1[rr] += qv * kv1;
            }
        }

        #pragma unroll
        for (int rr = 0; rr < 8; rr++) {
            const int qi = q0 + w * 8 + rr;
            float s0 = (k0 + lane      <= qi) ? sc0[rr] * 0.125f : -INFINITY;
            float s1 = (k0 + lane + 32 <= qi) ? sc1[rr] * 0.125f : -INFINITY;
            float tmax = fmaxf(s0, s1);
            #pragma unroll
            for (int off = 16; off > 0; off >>= 1)
                tmax = fmaxf(tmax, __shfl_xor_sync(0xffffffffu, tmax, off));
            const float nm = fmaxf(m[rr], tmax);
            const float scale = __expf(m[rr] - nm);
            const float p0 = __expf(s0 - nm);
            const float p1 = __expf(s1 - nm);
            float ps = p0 + p1;
            #pragma unroll
            for (int off = 16; off > 0; off >>= 1)
                ps += __shfl_xor_sync(0xffffffffu, ps, off);
            l[rr] = l[rr] * scale + ps;
            m[rr] = nm;
            acc0[rr] *= scale;
            acc1[rr] *= scale;
            Ps[(w * 8 + rr) * 64 + lane]      = p0;
            Ps[(w * 8 + rr) * 64 + lane + 32] = p1;
        }
        __syncwarp();

        #pragma unroll 4
        for (int k = 0; k < 64; k++) {
            const float v0 = Vs[k * 64 + lane];
            const float v1 = Vs[k * 64 + lane + 32];
            #pragma unroll
            for (int rr = 0; rr < 8; rr++) {
                const float p = Ps[(w * 8 + rr) * 64 + k];
                acc0[rr] += p * v0;
                acc1[rr] += p * v1;
            }
        }
    }

    const int b = bh >> 4, h = bh & 15;
    #pragma unroll
    for (int rr = 0; rr < 8; rr++) {
        const float inv = 1.0f / l[rr];
        const int t = q0 + w * 8 + rr;
        float* op = O + ((size_t)(b * TSEQ + t)) * EMBED + h * HDIM;
        op[lane]      = acc0[rr] * inv;
        op[lane + 32] = acc1[rr] * inv;
    }
}

// ================= launch =================
extern "C" void kernel_launch(void* const* d_in, const int* in_sizes, int n_in,
                              void* d_out, int out_size)
{
    const float* x  = (const float*)d_in[0];
    const float* Wq = (const float*)d_in[1];
    const float* bq = (const float*)d_in[2];
    const float* Wk = (const float*)d_in[3];
    const float* bk = (const float*)d_in[4];
    const float* Wv = (const float*)d_in[5];
    const float* bv = (const float*)d_in[6];
    const float* Wp = (const float*)d_in[7];
    const float* bp = (const float*)d_in[8];
    float* out = (float*)d_out;

    float *q, *k, *v, *o;
    __nv_bfloat16 *xhi, *xlo, *ohi, *olo, *wthi, *wtlo;
    cudaGetSymbolAddress((void**)&q, g_q);
    cudaGetSymbolAddress((void**)&k, g_k);
    cudaGetSymbolAddress((void**)&v, g_v);
    cudaGetSymbolAddress((void**)&o, g_o);
    cudaGetSymbolAddress((void**)&xhi, g_xhi);
    cudaGetSymbolAddress((void**)&xlo, g_xlo);
    cudaGetSymbolAddress((void**)&ohi, g_ohi);
    cudaGetSymbolAddress((void**)&olo, g_olo);
    cudaGetSymbolAddress((void**)&wthi, g_wthi);
    cudaGetSymbolAddress((void**)&wtlo, g_wtlo);

    const int gemm_smem = 2 * 65536;  // 131072
    cudaFuncSetAttribute(mma_gemm<true >, cudaFuncAttributeMaxDynamicSharedMemorySize, gemm_smem);
    cudaFuncSetAttribute(mma_gemm<false>, cudaFuncAttributeMaxDynamicSharedMemorySize, gemm_smem);
    const int attn_smem = (64 * 64 + 64 * 65 + 64 * 64 + 64 * 64) * (int)sizeof(float);
    cudaFuncSetAttribute(attn_kernel, cudaFuncAttributeMaxDynamicSharedMemorySize, attn_smem);

    const size_t WN = (size_t)EMBED * EMBED;

    split_f32<<<(MROWS * EMBED / 4 + 255) / 256, 256>>>(x, xhi, xlo, MROWS * EMBED / 4);
    dim3 tgrid(EMBED / 32, EMBED / 32);
    dim3 tblk(32, 8);
    transpose_split<<<tgrid, tblk>>>(Wq, wthi + 0 * WN, wtlo + 0 * WN);
    transpose_split<<<tgrid, tblk>>>(Wk, wthi + 1 * WN, wtlo + 1 * WN);
    transpose_split<<<tgrid, tblk>>>(Wv, wthi + 2 * WN, wtlo + 2 * WN);
    transpose_split<<<tgrid, tblk>>>(Wp, wthi + 3 * WN, wtlo + 3 * WN);

    dim3 ggrid(EMBED / 128, MROWS / 128);  // (8, 64)
    mma_gemm<true ><<<ggrid, 256, gemm_smem>>>(xhi, xlo, wthi + 0 * WN, wtlo + 0 * WN, bq, q);
    mma_gemm<true ><<<ggrid, 256, gemm_smem>>>(xhi, xlo, wthi + 1 * WN, wtlo + 1 * WN, bk, k);
    mma_gemm<true ><<<ggrid, 256, gemm_smem>>>(xhi, xlo, wthi + 2 * WN, wtlo + 2 * WN, bv, v);

    dim3 agrid(TSEQ / 64, BATCH * HEADS);
    attn_kernel<<<agrid, 256, attn_smem>>>(q, k, v, o);

    split_f32<<<(MROWS * EMBED / 4 + 255) / 256, 256>>>(o, ohi, olo, MROWS * EMBED / 4);
    mma_gemm<false><<<ggrid, 256, gemm_smem>>>(ohi, olo, wthi + 3 * WN, wtlo + 3 * WN, bp, out);

    (void)in_sizes; (void)n_in; (void)out_size;
}

// round 4
// speedup vs baseline: 3.6110x; 1.8503x over previous
#include <cuda_runtime.h>
#include <cuda_bf16.h>
#include <math.h>
#include <stdint.h>

#define EMBED   1024
#define HEADS   16
#define HDIM    64
#define BATCH   4
#define TSEQ    2048
#define MROWS   (BATCH * TSEQ)   // 8192

// ================= helpers =================
__device__ __forceinline__ uint32_t smem_u32(const void* p) {
    uint32_t a;
    asm("{ .reg .u64 t; cvta.to.shared.u64 t, %1; cvt.u32.u64 %0, t; }" : "=r"(a) : "l"(p));
    return a;
}
__device__ __forceinline__ uint32_t swz128(uint32_t off) { return off ^ ((off >> 3) & 0x70); }

__device__ __forceinline__ void cp_async16(uint32_t dst, const void* src) {
    asm volatile("cp.async.cg.shared.global [%0], [%1], 16;" :: "r"(dst), "l"(src));
}
#define CP_COMMIT() asm volatile("cp.async.commit_group;" ::: "memory")
#define CP_WAIT(n)  asm volatile("cp.async.wait_group %0;" :: "n"(n) : "memory")

__device__ __forceinline__ void ldsm_x4(uint32_t* r, uint32_t addr) {
    asm volatile("ldmatrix.sync.aligned.m8n8.x4.shared.b16 {%0,%1,%2,%3}, [%4];"
        : "=r"(r[0]), "=r"(r[1]), "=r"(r[2]), "=r"(r[3]) : "r"(addr));
}
__device__ __forceinline__ void ldsm_x4_t(uint32_t* r, uint32_t addr) {
    asm volatile("ldmatrix.sync.aligned.m8n8.x4.trans.shared.b16 {%0,%1,%2,%3}, [%4];"
        : "=r"(r[0]), "=r"(r[1]), "=r"(r[2]), "=r"(r[3]) : "r"(addr));
}
__device__ __forceinline__ void mma16816(float* d, const uint32_t* a, const uint32_t* b) {
    asm volatile("mma.sync.aligned.m16n8k16.row.col.f32.bf16.bf16.f32 "
        "{%0,%1,%2,%3}, {%4,%5,%6,%7}, {%8,%9}, {%0,%1,%2,%3};"
        : "+f"(d[0]), "+f"(d[1]), "+f"(d[2]), "+f"(d[3])
        : "r"(a[0]), "r"(a[1]), "r"(a[2]), "r"(a[3]), "r"(b[0]), "r"(b[1]));
}
// split two floats into bf16-hi pair + bf16-lo(residual) pair, packed u32
__device__ __forceinline__ void split_pack(float x, float y, uint32_t& hi, uint32_t& lo) {
    __nv_bfloat16 hx = __float2bfloat16(x), hy = __float2bfloat16(y);
    float rx = x - __bfloat162float(hx), ry = y - __bfloat162float(hy);
    __nv_bfloat16 lx = __float2bfloat16(rx), ly = __float2bfloat16(ry);
    hi = (uint32_t)__bfloat16_as_ushort(hx) | ((uint32_t)__bfloat16_as_ushort(hy) << 16);
    lo = (uint32_t)__bfloat16_as_ushort(lx) | ((uint32_t)__bfloat16_as_ushort(ly) << 16);
}

// ================= scratch =================
__device__ __nv_bfloat16 g_qh[BATCH * HEADS * TSEQ * HDIM];
__device__ __nv_bfloat16 g_ql[BATCH * HEADS * TSEQ * HDIM];
__device__ __nv_bfloat16 g_kh[BATCH * HEADS * TSEQ * HDIM];
__device__ __nv_bfloat16 g_kl[BATCH * HEADS * TSEQ * HDIM];
__device__ __nv_bfloat16 g_vh[BATCH * HEADS * TSEQ * HDIM];
__device__ __nv_bfloat16 g_vl[BATCH * HEADS * TSEQ * HDIM];
__device__ __nv_bfloat16 g_ohi[MROWS * EMBED];
__device__ __nv_bfloat16 g_olo[MROWS * EMBED];
__device__ __nv_bfloat16 g_xhi[MROWS * EMBED];
__device__ __nv_bfloat16 g_xlo[MROWS * EMBED];
__device__ __nv_bfloat16 g_wthi[4 * EMBED * EMBED];   // Wt[N,K] per weight
__device__ __nv_bfloat16 g_wtlo[4 * EMBED * EMBED];

// ================= split conversion (x) =================
__global__ __launch_bounds__(256)
void split_f32(const float* __restrict__ in, __nv_bfloat16* __restrict__ hi,
               __nv_bfloat16* __restrict__ lo, int n4)
{
    int i = blockIdx.x * blockDim.x + threadIdx.x;
    if (i >= n4) return;
    float4 v = ((const float4*)in)[i];
    uint32_t h0, l0, h1, l1;
    split_pack(v.x, v.y, h0, l0);
    split_pack(v.z, v.w, h1, l1);
    ((uint2*)hi)[i] = make_uint2(h0, h1);
    ((uint2*)lo)[i] = make_uint2(l0, l1);
}

// ================= transpose + split (W[K,N] -> Wt[N,K] hi/lo) =================
__global__ __launch_bounds__(256)
void transpose_split(const float* __restrict__ W, __nv_bfloat16* __restrict__ hi,
                     __nv_bfloat16* __restrict__ lo)
{
    __shared__ float t[32][33];
    const int bx = blockIdx.x * 32;   // N
    const int by = blockIdx.y * 32;   // K
    const int x = threadIdx.x, y = threadIdx.y;  // 32 x 8
    #pragma unroll
    for (int j = 0; j < 32; j += 8)
        t[y + j][x] = W[(size_t)(by + y + j) * EMBED + bx + x];
    __syncthreads();
    #pragma unroll
    for (int j = 0; j < 32; j += 8) {
        float v = t[x][y + j];
        __nv_bfloat16 h = __float2bfloat16(v);
        __nv_bfloat16 l = __float2bfloat16(v - __bfloat162float(h));
        size_t idx = (size_t)(bx + y + j) * EMBED + by + x;
        hi[idx] = h;
        lo[idx] = l;
    }
}

// ================= HMMA bf16x3 GEMM =================
// C = A[M,K] * Wt[N,K]^T + bias, then *scale.
// SPLIT: write bf16 hi/lo into (B,H,T,D). else: f32 into [M,N].
template<bool SPLIT>
__global__ __launch_bounds__(256)
void mma_gemm(const __nv_bfloat16* __restrict__ Ahi, const __nv_bfloat16* __restrict__ Alo,
              const __nv_bfloat16* __restrict__ Bhi, const __nv_bfloat16* __restrict__ Blo,
              const float* __restrict__ bias, float scale,
              float* __restrict__ Cf,
              __nv_bfloat16* __restrict__ Chi, __nv_bfloat16* __restrict__ Clo)
{
    constexpr int K = EMBED, NG = EMBED;
    constexpr int BK = 64, NK = K / BK;
    constexpr int TILE_B = 128 * BK * 2;     // 16384
    constexpr int STAGE_B = 4 * TILE_B;      // 65536
    extern __shared__ __align__(1024) char smem[];
    const uint32_t sb = smem_u32(smem);
    const int tid = threadIdx.x, wid = tid >> 5, lane = tid & 31;
    const int n0 = blockIdx.x * 128, m0 = blockIdx.y * 128;
    const int warp_m = wid & 3, warp_n = wid >> 2;

    const __nv_bfloat16* srcs[4] = {Ahi, Alo, Bhi, Blo};

    auto load_chunk = [&](int kt, int s) {
        #pragma unroll
        for (int t = 0; t < 4; t++) {
            const __nv_bfloat16* base = srcs[t] + (size_t)((t < 2) ? m0 : n0) * K + kt * BK;
            const uint32_t tb = sb + s * STAGE_B + t * TILE_B;
            #pragma unroll
            for (int i = 0; i < 4; i++) {
                int chunk = tid + i * 256;
                int r = chunk >> 3, c = chunk & 7;
                cp_async16(tb + swz128(r * 128 + c * 16), base + (size_t)r * K + c * 8);
            }
        }
        CP_COMMIT();
    };

    float acc[2][8][4];
    #pragma unroll
    for (int mb = 0; mb < 2; mb++)
        #pragma unroll
        for (int nb = 0; nb < 8; nb++)
            #pragma unroll
            for (int j = 0; j < 4; j++) acc[mb][nb][j] = 0.f;

    const int a_row = warp_m * 32 + (lane & 7) + ((lane >> 3) & 1) * 8;
    const int a_col = (lane >> 4) * 16;
    const int b_row = warp_n * 64 + (lane & 7) + (lane >> 4) * 8;
    const int b_col = ((lane >> 3) & 1) * 16;

    load_chunk(0, 0);
    for (int kt = 0; kt < NK; kt++) {
        const int cur = kt & 1;
        if (kt + 1 < NK) { load_chunk(kt + 1, cur ^ 1); CP_WAIT(1); }
        else             { CP_WAIT(0); }
        __syncthreads();

        const uint32_t tAh = sb + cur * STAGE_B + 0 * TILE_B;
        const uint32_t tAl = sb + cur * STAGE_B + 1 * TILE_B;
        const uint32_t tBh = sb + cur * STAGE_B + 2 * TILE_B;
        const uint32_t tBl = sb + cur * STAGE_B + 3 * TILE_B;

        #pragma unroll
        for (int ks = 0; ks < 4; ks++) {
            uint32_t ah[2][4], al[2][4], bh[4][4], bl[4][4];
            #pragma unroll
            for (int mb = 0; mb < 2; mb++) {
                const uint32_t off = swz128((a_row + mb * 16) * 128 + a_col + ks * 32);
                ldsm_x4(ah[mb], tAh + off);
                ldsm_x4(al[mb], tAl + off);
            }
            #pragma unroll
            for (int nb = 0; nb < 4; nb++) {
                const uint32_t off = swz128((b_row + nb * 16) * 128 + b_col + ks * 32);
                ldsm_x4(bh[nb], tBh + off);
                ldsm_x4(bl[nb], tBl + off);
            }
            #pragma unroll
            for (int mb = 0; mb < 2; mb++)
                #pragma unroll
                for (int nb = 0; nb < 4; nb++)
                    #pragma unroll
                    for (int h = 0; h < 2; h++) {
                        float* d = acc[mb][nb * 2 + h];
                        mma16816(d, ah[mb], &bh[nb][h * 2]);
                        mma16816(d, ah[mb], &bl[nb][h * 2]);
                        mma16816(d, al[mb], &bh[nb][h * 2]);
                    }
        }
        __syncthreads();
    }

    const int er = m0 + warp_m * 32 + (lane >> 2);
    const int ec = n0 + warp_n * 64 + (lane & 3) * 2;
    #pragma unroll
    for (int mb = 0; mb < 2; mb++) {
        #pragma unroll
        for (int half = 0; half < 2; half++) {
            const int row = er + mb * 16 + half * 8;
            #pragma unroll
            for (int nb = 0; nb < 8; nb++) {
                const int col = ec + nb * 8;
                const float v0 = (acc[mb][nb][half * 2 + 0] + bias[col]) * scale;
                const float v1 = (acc[mb][nb][half * 2 + 1] + bias[col + 1]) * scale;
                if (SPLIT) {
                    const int b = row / TSEQ, t = row % TSEQ;
                    const int hh = col >> 6, dd = col & 63;
                    const size_t idx = (((size_t)(b * HEADS + hh)) * TSEQ + t) * HDIM + dd;
                    uint32_t hi, lo;
                    split_pack(v0, v1, hi, lo);
                    *(uint32_t*)(Chi + idx) = hi;
                    *(uint32_t*)(Clo + idx) = lo;
                } else {
                    float* dst = Cf + (size_t)row * NG + col;
                    dst[0] = v0;
                    dst[1] = v1;
                }
            }
        }
    }
}

// ================= HMMA bf16x3 causal flash attention =================
// Grid (T/128, B*H), 256 threads = 8 warps; warp owns 16 q rows.
// Q tile 128x64 (hi/lo), K/V tiles 64x64 (hi/lo), double-buffered.
__global__ __launch_bounds__(256, 1)
void attn_mma(const __nv_bfloat16* __restrict__ qh_, const __nv_bfloat16* __restrict__ ql_,
              const __nv_bfloat16* __restrict__ kh_, const __nv_bfloat16* __restrict__ kl_,
              const __nv_bfloat16* __restrict__ vh_, const __nv_bfloat16* __restrict__ vl_,
              __nv_bfloat16* __restrict__ Ohi, __nv_bfloat16* __restrict__ Olo)
{
    extern __shared__ __align__(1024) char smem[];
    const uint32_t sb = smem_u32(smem);
    const int qt = blockIdx.x, bh = blockIdx.y;
    const int tid = threadIdx.x, wm = tid >> 5, lane = tid & 31;
    const int q0 = qt * 128;
    const size_t gbase = (size_t)bh * TSEQ * HDIM;

    // smem: Qh[16K] Ql[16K] | stage0: Kh Kl Vh Vl (8K each) | stage1: same
    const uint32_t QH = sb, QL = sb + 16384;
    const uint32_t ST = sb + 32768;

    // load Q hi/lo
    {
        const __nv_bfloat16* s0 = qh_ + gbase + (size_t)q0 * HDIM;
        const __nv_bfloat16* s1 = ql_ + gbase + (size_t)q0 * HDIM;
        #pragma unroll
        for (int i = 0; i < 4; i++) {
            int c = tid + i * 256;             // 0..1023
            int row = c >> 3, cc = c & 7;
            uint32_t off = swz128(row * 128 + cc * 16);
            cp_async16(QH + off, s0 + (size_t)row * HDIM + cc * 8);
            cp_async16(QL + off, s1 + (size_t)row * HDIM + cc * 8);
        }
    }
    auto load_kv = [&](int kt, int s) {
        const int k0 = kt * 64;
        const __nv_bfloat16* srcs[4] = {kh_ + gbase + (size_t)k0 * HDIM, kl_ + gbase + (size_t)k0 * HDIM,
                                        vh_ + gbase + (size_t)k0 * HDIM, vl_ + gbase + (size_t)k0 * HDIM};
        #pragma unroll
        for (int t = 0; t < 4; t++) {
            uint32_t dstb = ST + s * 32768 + t * 8192;
            #pragma unroll
            for (int i = 0; i < 2; i++) {
                int c = tid + i * 256;          // 0..511
                int row = c >> 3, cc = c & 7;
                cp_async16(dstb + swz128(row * 128 + cc * 16), srcs[t] + (size_t)row * HDIM + cc * 8);
            }
        }
    };
    load_kv(0, 0);
    CP_COMMIT();

    float m0 = -INFINITY, m1 = -INFINITY, l0 = 0.f, l1 = 0.f;
    float oacc[8][4];
    #pragma unroll
    for (int nb = 0; nb < 8; nb++)
        #pragma unroll
        for (int j = 0; j < 4; j++) oacc[nb][j] = 0.f;

    const int r = lane >> 2, tig = lane & 3;
    const int a_row = wm * 16 + (lane & 7) + ((lane >> 3) & 1) * 8;
    const int a_colb = (lane >> 4) * 16;
    const int b_rowK = (lane & 7) + (lane >> 4) * 8;       // + nb16*16
    const int b_colbK = ((lane >> 3) & 1) * 16;            // + ks*32
    const int v_row = (lane & 7) + ((lane >> 3) & 1) * 8;  // + 16*j
    const int v_colb = (lane >> 4) * 16;                   // + nb16*32

    const int nk = 2 * qt + 2;
    for (int kt = 0; kt < nk; kt++) {
        const int cur = kt & 1;
        if (kt + 1 < nk) { load_kv(kt + 1, cur ^ 1); CP_COMMIT(); CP_WAIT(1); }
        else             { CP_WAIT(0); }
        __syncthreads();
        const int k0 = kt * 64;
        const uint32_t KH = ST + cur * 32768, KL = KH + 8192, VH = KH + 16384, VL = KH + 24576;
        const bool active = (k0 <= q0 + wm * 16 + 15);
        if (active) {
            // ---- S = Q K^T (3-term) ----
            float sacc[8][4];
            #pragma unroll
            for (int nb = 0; nb < 8; nb++)
                #pragma unroll
                for (int j = 0; j < 4; j++) sacc[nb][j] = 0.f;
            #pragma unroll
            for (int ks = 0; ks < 4; ks++) {
                uint32_t ah[4], al[4];
                const uint32_t aoff = swz128(a_row * 128 + a_colb + ks * 32);
                ldsm_x4(ah, QH + aoff);
                ldsm_x4(al, QL + aoff);
                #pragma unroll
                for (int nb16 = 0; nb16 < 4; nb16++) {
                    uint32_t bh4[4], bl4[4];
                    const uint32_t boff = swz128((nb16 * 16 + b_rowK) * 128 + b_colbK + ks * 32);
                    ldsm_x4(bh4, KH + boff);
                    ldsm_x4(bl4, KL + boff);
                    #pragma unroll
                    for (int h = 0; h < 2; h++) {
                        float* d = sacc[nb16 * 2 + h];
                        mma16816(d, ah, &bh4[h * 2]);
                        mma16816(d, ah, &bl4[h * 2]);
                        mma16816(d, al, &bh4[h * 2]);
                    }
                }
            }
            // ---- causal mask ----
            if (k0 + 63 > q0 + wm * 16) {
                #pragma unroll
                for (int nb = 0; nb < 8; nb++)
                    #pragma unroll
                    for (int j = 0; j < 4; j++) {
                        const int qrow = q0 + wm * 16 + r + (j >> 1) * 8;
                        const int kcol = k0 + nb * 8 + tig * 2 + (j & 1);
                        if (kcol > qrow) sacc[nb][j] = -INFINITY;
                    }
            }
            // ---- online softmax (rows r and r+8) ----
            float rx0 = -INFINITY, rx1 = -INFINITY;
            #pragma unroll
            for (int nb = 0; nb < 8; nb++) {
                rx0 = fmaxf(rx0, fmaxf(sacc[nb][0], sacc[nb][1]));
                rx1 = fmaxf(rx1, fmaxf(sacc[nb][2], sacc[nb][3]));
            }
            #pragma unroll
            for (int off = 1; off <= 2; off <<= 1) {
                rx0 = fmaxf(rx0, __shfl_xor_sync(0xffffffffu, rx0, off));
                rx1 = fmaxf(rx1, __shfl_xor_sync(0xffffffffu, rx1, off));
            }
            const float nm0 = fmaxf(m0, rx0), nm1 = fmaxf(m1, rx1);
            const float sc0 = __expf(m0 - nm0), sc1 = __expf(m1 - nm1);
            float rs0 = 0.f, rs1 = 0.f;
            #pragma unroll
            for (int nb = 0; nb < 8; nb++) {
                sacc[nb][0] = __expf(sacc[nb][0] - nm0);
                sacc[nb][1] = __expf(sacc[nb][1] - nm0);
                sacc[nb][2] = __expf(sacc[nb][2] - nm1);
                sacc[nb][3] = __expf(sacc[nb][3] - nm1);
                rs0 += sacc[nb][0] + sacc[nb][1];
                rs1 += sacc[nb][2] + sacc[nb][3];
            }
            #pragma unroll
            for (int off = 1; off <= 2; off <<= 1) {
                rs0 += __shfl_xor_sync(0xffffffffu, rs0, off);
                rs1 += __shfl_xor_sync(0xffffffffu, rs1, off);
            }
            l0 = l0 * sc0 + rs0;
            l1 = l1 * sc1 + rs1;
            m0 = nm0; m1 = nm1;
            #pragma unroll
            for (int nb = 0; nb < 8; nb++) {
                oacc[nb][0] *= sc0; oacc[nb][1] *= sc0;
                oacc[nb][2] *= sc1; oacc[nb][3] *= sc1;
            }
            // ---- O += P V (3-term), P split in registers ----
            #pragma unroll
            for (int j = 0; j < 4; j++) {
                uint32_t pah[4], pal[4];
                split_pack(sacc[2 * j][0],     sacc[2 * j][1],     pah[0], pal[0]);
                split_pack(sacc[2 * j][2],     sacc[2 * j][3],     pah[1], pal[1]);
                split_pack(sacc[2 * j + 1][0], sacc[2 * j + 1][1], pah[2], pal[2]);
                split_pack(sacc[2 * j + 1][2], sacc[2 * j + 1][3], pah[3], pal[3]);
                #pragma unroll
                for (int nb16 = 0; nb16 < 4; nb16++) {
                    uint32_t vh4[4], vl4[4];
                    const uint32_t voff = swz128((16 * j + v_row) * 128 + nb16 * 32 + v_colb);
                    ldsm_x4_t(vh4, VH + voff);
                    ldsm_x4_t(vl4, VL + voff);
                    #pragma unroll
                    for (int h = 0; h < 2; h++) {
                        float* d = oacc[nb16 * 2 + h];
                        mma16816(d, pah, &vh4[h * 2]);
                        mma16816(d, pah, &vl4[h * 2]);
                        mma16816(d, pal, &vh4[h * 2]);
                    }
                }
            }
        }
        __syncthreads();
    }

    // ---- epilogue: write o as bf16 hi/lo into (B,T,C) ----
    const float inv0 = 1.0f / l0, inv1 = 1.0f / l1;
    const int b = bh >> 4, h = bh & 15;
    #pragma unroll
    for (int half = 0; half < 2; half++) {
        const int t = q0 + wm * 16 + r + half * 8;
        const float inv = half ? inv1 : inv0;
        const size_t off = ((size_t)(b * TSEQ + t)) * EMBED + h * HDIM;
        #pragma unroll
        for (int nb = 0; nb < 8; nb++) {
            const float v0 = oacc[nb][half * 2 + 0] * inv;
            const float v1 = oacc[nb][half * 2 + 1] * inv;
            uint32_t hi, lo;
            split_pack(v0, v1, hi, lo);
            *(uint32_t*)(Ohi + off + nb * 8 + tig * 2) = hi;
            *(uint32_t*)(Olo + off + nb * 8 + tig * 2) = lo;
        }
    }
}

// ================= launch =================
extern "C" void kernel_launch(void* const* d_in, const int* in_sizes, int n_in,
                              void* d_out, int out_size)
{
    const float* x  = (const float*)d_in[0];
    const float* Wq = (const float*)d_in[1];
    const float* bq = (const float*)d_in[2];
    const float* Wk = (const float*)d_in[3];
    const float* bk = (const float*)d_in[4];
    const float* Wv = (const float*)d_in[5];
    const float* bv = (const float*)d_in[6];
    const float* Wp = (const float*)d_in[7];
    const float* bp = (const float*)d_in[8];
    float* out = (float*)d_out;

    __nv_bfloat16 *qh, *ql, *kh, *kl, *vh, *vl, *ohi, *olo, *xhi, *xlo, *wthi, *wtlo;
    cudaGetSymbolAddress((void**)&qh, g_qh);
    cudaGetSymbolAddress((void**)&ql, g_ql);
    cudaGetSymbolAddress((void**)&kh, g_kh);
    cudaGetSymbolAddress((void**)&kl, g_kl);
    cudaGetSymbolAddress((void**)&vh, g_vh);
    cudaGetSymbolAddress((void**)&vl, g_vl);
    cudaGetSymbolAddress((void**)&ohi, g_ohi);
    cudaGetSymbolAddress((void**)&olo, g_olo);
    cudaGetSymbolAddress((void**)&xhi, g_xhi);
    cudaGetSymbolAddress((void**)&xlo, g_xlo);
    cudaGetSymbolAddress((void**)&wthi, g_wthi);
    cudaGetSymbolAddress((void**)&wtlo, g_wtlo);

    const int gemm_smem = 2 * 65536;
    cudaFuncSetAttribute(mma_gemm<true >, cudaFuncAttributeMaxDynamicSharedMemorySize, gemm_smem);
    cudaFuncSetAttribute(mma_gemm<false>, cudaFuncAttributeMaxDynamicSharedMemorySize, gemm_smem);
    const int attn_smem = 32768 + 2 * 32768;  // 98304
    cudaFuncSetAttribute(attn_mma, cudaFuncAttributeMaxDynamicSharedMemorySize, attn_smem);

    const size_t WN = (size_t)EMBED * EMBED;

    split_f32<<<(MROWS * EMBED / 4 + 255) / 256, 256>>>(x, xhi, xlo, MROWS * EMBED / 4);
    dim3 tgrid(EMBED / 32, EMBED / 32);
    dim3 tblk(32, 8);
    transpose_split<<<tgrid, tblk>>>(Wq, wthi + 0 * WN, wtlo + 0 * WN);
    transpose_split<<<tgrid, tblk>>>(Wk, wthi + 1 * WN, wtlo + 1 * WN);
    transpose_split<<<tgrid, tblk>>>(Wv, wthi + 2 * WN, wtlo + 2 * WN);
    transpose_split<<<tgrid, tblk>>>(Wp, wthi + 3 * WN, wtlo + 3 * WN);

    dim3 ggrid(EMBED / 128, MROWS / 128);  // (8, 64)
    // softmax 1/sqrt(64) folded into Q projection scale
    mma_gemm<true ><<<ggrid, 256, gemm_smem>>>(xhi, xlo, wthi + 0 * WN, wtlo + 0 * WN, bq, 0.125f, nullptr, qh, ql);
    mma_gemm<true ><<<ggrid, 256, gemm_smem>>>(xhi, xlo, wthi + 1 * WN, wtlo + 1 * WN, bk, 1.0f,   nullptr, kh, kl);
    mma_gemm<true ><<<ggrid, 256, gemm_smem>>>(xhi, xlo, wthi + 2 * WN, wtlo + 2 * WN, bv, 1.0f,   nullptr, vh, vl);

    dim3 agrid(TSEQ / 128, BATCH * HEADS);  // (16, 64)
    attn_mma<<<agrid, 256, attn_smem>>>(qh, ql, kh, kl, vh, vl, ohi, olo);

    mma_gemm<false><<<ggrid, 256, gemm_smem>>>(ohi, olo, wthi + 3 * WN, wtlo + 3 * WN, bp, 1.0f, out, nullptr, nullptr);

    (void)in_sizes; (void)n_in; (void)out_size;
}

// round 5
// speedup vs baseline: 3.7260x; 1.0318x over previous
#include <cuda_runtime.h>
#include <cuda_bf16.h>
#include <math.h>
#include <stdint.h>

#define EMBED   1024
#define HEADS   16
#define HDIM    64
#define BATCH   4
#define TSEQ    2048
#define MROWS   (BATCH * TSEQ)   // 8192

// ================= helpers =================
__device__ __forceinline__ uint32_t smem_u32(const void* p) {
    uint32_t a;
    asm("{ .reg .u64 t; cvta.to.shared.u64 t, %1; cvt.u32.u64 %0, t; }" : "=r"(a) : "l"(p));
    return a;
}
__device__ __forceinline__ uint32_t swz128(uint32_t off) { return off ^ ((off >> 3) & 0x70); }

__device__ __forceinline__ void cp_async16(uint32_t dst, const void* src) {
    asm volatile("cp.async.cg.shared.global [%0], [%1], 16;" :: "r"(dst), "l"(src));
}
#define CP_COMMIT() asm volatile("cp.async.commit_group;" ::: "memory")
#define CP_WAIT(n)  asm volatile("cp.async.wait_group %0;" :: "n"(n) : "memory")

__device__ __forceinline__ void ldsm_x4(uint32_t* r, uint32_t addr) {
    asm volatile("ldmatrix.sync.aligned.m8n8.x4.shared.b16 {%0,%1,%2,%3}, [%4];"
        : "=r"(r[0]), "=r"(r[1]), "=r"(r[2]), "=r"(r[3]) : "r"(addr));
}
__device__ __forceinline__ void ldsm_x4_t(uint32_t* r, uint32_t addr) {
    asm volatile("ldmatrix.sync.aligned.m8n8.x4.trans.shared.b16 {%0,%1,%2,%3}, [%4];"
        : "=r"(r[0]), "=r"(r[1]), "=r"(r[2]), "=r"(r[3]) : "r"(addr));
}
__device__ __forceinline__ void mma16816(float* d, const uint32_t* a, const uint32_t* b) {
    asm volatile("mma.sync.aligned.m16n8k16.row.col.f32.bf16.bf16.f32 "
        "{%0,%1,%2,%3}, {%4,%5,%6,%7}, {%8,%9}, {%0,%1,%2,%3};"
        : "+f"(d[0]), "+f"(d[1]), "+f"(d[2]), "+f"(d[3])
        : "r"(a[0]), "r"(a[1]), "r"(a[2]), "r"(a[3]), "r"(b[0]), "r"(b[1]));
}
__device__ __forceinline__ void split_pack(float x, float y, uint32_t& hi, uint32_t& lo) {
    __nv_bfloat16 hx = __float2bfloat16(x), hy = __float2bfloat16(y);
    float rx = x - __bfloat162float(hx), ry = y - __bfloat162float(hy);
    __nv_bfloat16 lx = __float2bfloat16(rx), ly = __float2bfloat16(ry);
    hi = (uint32_t)__bfloat16_as_ushort(hx) | ((uint32_t)__bfloat16_as_ushort(hy) << 16);
    lo = (uint32_t)__bfloat16_as_ushort(lx) | ((uint32_t)__bfloat16_as_ushort(ly) << 16);
}

// ================= scratch =================
__device__ __nv_bfloat16 g_qh[BATCH * HEADS * TSEQ * HDIM];
__device__ __nv_bfloat16 g_ql[BATCH * HEADS * TSEQ * HDIM];
__device__ __nv_bfloat16 g_kh[BATCH * HEADS * TSEQ * HDIM];
__device__ __nv_bfloat16 g_kl[BATCH * HEADS * TSEQ * HDIM];
__device__ __nv_bfloat16 g_vh[BATCH * HEADS * TSEQ * HDIM];
__device__ __nv_bfloat16 g_vl[BATCH * HEADS * TSEQ * HDIM];
__device__ __nv_bfloat16 g_ohi[MROWS * EMBED];
__device__ __nv_bfloat16 g_olo[MROWS * EMBED];
__device__ __nv_bfloat16 g_xhi[MROWS * EMBED];
__device__ __nv_bfloat16 g_xlo[MROWS * EMBED];
__device__ __nv_bfloat16 g_wthi[4 * EMBED * EMBED];   // Wt[N,K] per weight
__device__ __nv_bfloat16 g_wtlo[4 * EMBED * EMBED];

// softmax exp2 fold: Q scaled by 1/8 * log2(e)
#define QSCALE (0.125f * 1.4426950408889634f)

// ================= split conversion (x) =================
__global__ __launch_bounds__(256)
void split_f32(const float* __restrict__ in, __nv_bfloat16* __restrict__ hi,
               __nv_bfloat16* __restrict__ lo, int n4)
{
    int i = blockIdx.x * blockDim.x + threadIdx.x;
    if (i >= n4) return;
    float4 v = ((const float4*)in)[i];
    uint32_t h0, l0, h1, l1;
    split_pack(v.x, v.y, h0, l0);
    split_pack(v.z, v.w, h1, l1);
    ((uint2*)hi)[i] = make_uint2(h0, h1);
    ((uint2*)lo)[i] = make_uint2(l0, l1);
}

// ================= transpose + split (W[K,N] -> Wt[N,K] hi/lo) =================
__global__ __launch_bounds__(256)
void transpose_split(const float* __restrict__ W, __nv_bfloat16* __restrict__ hi,
                     __nv_bfloat16* __restrict__ lo)
{
    __shared__ float t[32][33];
    const int bx = blockIdx.x * 32;   // N
    const int by = blockIdx.y * 32;   // K
    const int x = threadIdx.x, y = threadIdx.y;  // 32 x 8
    #pragma unroll
    for (int j = 0; j < 32; j += 8)
        t[y + j][x] = W[(size_t)(by + y + j) * EMBED + bx + x];
    __syncthreads();
    #pragma unroll
    for (int j = 0; j < 32; j += 8) {
        float v = t[x][y + j];
        __nv_bfloat16 h = __float2bfloat16(v);
        __nv_bfloat16 l = __float2bfloat16(v - __bfloat162float(h));
        size_t idx = (size_t)(bx + y + j) * EMBED + by + x;
        hi[idx] = h;
        lo[idx] = l;
    }
}

// ================= GEMM core (bf16x3 HMMA) =================
struct GemmCore {
    uint32_t sb;
    int tid, wid, lane, warp_m, warp_n;
    float acc[2][8][4];
    int a_row, a_col, b_row, b_col;

    __device__ __forceinline__ void init(uint32_t sb_, int tid_) {
        sb = sb_; tid = tid_; wid = tid >> 5; lane = tid & 31;
        warp_m = wid & 3; warp_n = wid >> 2;
        #pragma unroll
        for (int mb = 0; mb < 2; mb++)
            #pragma unroll
            for (int nb = 0; nb < 8; nb++)
                #pragma unroll
                for (int j = 0; j < 4; j++) acc[mb][nb][j] = 0.f;
        a_row = warp_m * 32 + (lane & 7) + ((lane >> 3) & 1) * 8;
        a_col = (lane >> 4) * 16;
        b_row = warp_n * 64 + (lane & 7) + (lane >> 4) * 8;
        b_col = ((lane >> 3) & 1) * 16;
    }
};

#define TILE_B  16384     // 128 rows x 64 bf16 x 2
#define STAGE_B 65536     // 4 tiles

// fused QKV: grid (24, 64). widx = bx>>3 selects weight/output.
__global__ __launch_bounds__(256)
void qkv_gemm(const __nv_bfloat16* __restrict__ Ahi, const __nv_bfloat16* __restrict__ Alo,
              const __nv_bfloat16* __restrict__ Whi, const __nv_bfloat16* __restrict__ Wlo,
              const float* __restrict__ bq, const float* __restrict__ bk, const float* __restrict__ bv,
              __nv_bfloat16* __restrict__ qh, __nv_bfloat16* __restrict__ ql,
              __nv_bfloat16* __restrict__ kh, __nv_bfloat16* __restrict__ kl,
              __nv_bfloat16* __restrict__ vh, __nv_bfloat16* __restrict__ vl)
{
    constexpr int K = EMBED, NK = 16;
    extern __shared__ __align__(1024) char smem[];
    const uint32_t sb = smem_u32(smem);
    const int tid = threadIdx.x;
    const int widx = blockIdx.x >> 3;
    const int n0 = (blockIdx.x & 7) * 128, m0 = blockIdx.y * 128;
    const size_t WN = (size_t)EMBED * EMBED;

    const __nv_bfloat16* Bhi = Whi + (size_t)widx * WN;
    const __nv_bfloat16* Blo = Wlo + (size_t)widx * WN;
    const float* bias = (widx == 0) ? bq : (widx == 1) ? bk : bv;
    __nv_bfloat16* Chi = (widx == 0) ? qh : (widx == 1) ? kh : vh;
    __nv_bfloat16* Clo = (widx == 0) ? ql : (widx == 1) ? kl : vl;
    const float scale = (widx == 0) ? QSCALE : 1.0f;

    GemmCore g;
    g.init(sb, tid);
    const __nv_bfloat16* srcs[4] = {Ahi, Alo, Bhi, Blo};

    auto load_chunk = [&](int kt, int s) {
        #pragma unroll
        for (int t = 0; t < 4; t++) {
            const __nv_bfloat16* base = srcs[t] + (size_t)((t < 2) ? m0 : n0) * K + kt * 64;
            const uint32_t tb = sb + s * STAGE_B + t * TILE_B;
            #pragma unroll
            for (int i = 0; i < 4; i++) {
                int chunk = tid + i * 256;
                int r = chunk >> 3, c = chunk & 7;
                cp_async16(tb + swz128(r * 128 + c * 16), base + (size_t)r * K + c * 8);
            }
        }
        CP_COMMIT();
    };

    load_chunk(0, 0);
    for (int kt = 0; kt < NK; kt++) {
        const int cur = kt & 1;
        if (kt + 1 < NK) { load_chunk(kt + 1, cur ^ 1); CP_WAIT(1); }
        else             { CP_WAIT(0); }
        __syncthreads();
        const uint32_t tAh = sb + cur * STAGE_B, tAl = tAh + TILE_B, tBh = tAh + 2 * TILE_B, tBl = tAh + 3 * TILE_B;
        #pragma unroll
        for (int ks = 0; ks < 4; ks++) {
            uint32_t ah[2][4], al[2][4], bh[4][4], bl[4][4];
            #pragma unroll
            for (int mb = 0; mb < 2; mb++) {
                const uint32_t off = swz128((g.a_row + mb * 16) * 128 + g.a_col + ks * 32);
                ldsm_x4(ah[mb], tAh + off);
                ldsm_x4(al[mb], tAl + off);
            }
            #pragma unroll
            for (int nb = 0; nb < 4; nb++) {
                const uint32_t off = swz128((g.b_row + nb * 16) * 128 + g.b_col + ks * 32);
                ldsm_x4(bh[nb], tBh + off);
                ldsm_x4(bl[nb], tBl + off);
            }
            #pragma unroll
            for (int mb = 0; mb < 2; mb++)
                #pragma unroll
                for (int nb = 0; nb < 4; nb++)
                    #pragma unroll
                    for (int h = 0; h < 2; h++) {
                        float* d = g.acc[mb][nb * 2 + h];
                        mma16816(d, ah[mb], &bh[nb][h * 2]);
                        mma16816(d, ah[mb], &bl[nb][h * 2]);
                        mma16816(d, al[mb], &bh[nb][h * 2]);
                    }
        }
        __syncthreads();
    }

    const int er = m0 + g.warp_m * 32 + (g.lane >> 2);
    const int ec = n0 + g.warp_n * 64 + (g.lane & 3) * 2;
    #pragma unroll
    for (int mb = 0; mb < 2; mb++) {
        #pragma unroll
        for (int half = 0; half < 2; half++) {
            const int row = er + mb * 16 + half * 8;
            const int b = row / TSEQ, t = row % TSEQ;
            #pragma unroll
            for (int nb = 0; nb < 8; nb++) {
                const int col = ec + nb * 8;
                const float v0 = (g.acc[mb][nb][half * 2 + 0] + bias[col]) * scale;
                const float v1 = (g.acc[mb][nb][half * 2 + 1] + bias[col + 1]) * scale;
                const int hh = col >> 6, dd = col & 63;
                const size_t idx = (((size_t)(b * HEADS + hh)) * TSEQ + t) * HDIM + dd;
                uint32_t hi, lo;
                split_pack(v0, v1, hi, lo);
                *(uint32_t*)(Chi + idx) = hi;
                *(uint32_t*)(Clo + idx) = lo;
            }
        }
    }
}

// out-projection: f32 output [M,N]
__global__ __launch_bounds__(256)
void out_gemm(const __nv_bfloat16* __restrict__ Ahi, const __nv_bfloat16* __restrict__ Alo,
              const __nv_bfloat16* __restrict__ Bhi, const __nv_bfloat16* __restrict__ Blo,
              const float* __restrict__ bias, float* __restrict__ Cf)
{
    constexpr int K = EMBED, NG = EMBED, NK = 16;
    extern __shared__ __align__(1024) char smem[];
    const uint32_t sb = smem_u32(smem);
    const int tid = threadIdx.x;
    const int n0 = blockIdx.x * 128, m0 = blockIdx.y * 128;

    GemmCore g;
    g.init(sb, tid);
    const __nv_bfloat16* srcs[4] = {Ahi, Alo, Bhi, Blo};

    auto load_chunk = [&](int kt, int s) {
        #pragma unroll
        for (int t = 0; t < 4; t++) {
            const __nv_bfloat16* base = srcs[t] + (size_t)((t < 2) ? m0 : n0) * K + kt * 64;
            const uint32_t tb = sb + s * STAGE_B + t * TILE_B;
            #pragma unroll
            for (int i = 0; i < 4; i++) {
                int chunk = tid + i * 256;
                int r = chunk >> 3, c = chunk & 7;
                cp_async16(tb + swz128(r * 128 + c * 16), base + (size_t)r * K + c * 8);
            }
        }
        CP_COMMIT();
    };

    load_chunk(0, 0);
    for (int kt = 0; kt < NK; kt++) {
        const int cur = kt & 1;
        if (kt + 1 < NK) { load_chunk(kt + 1, cur ^ 1); CP_WAIT(1); }
        else             { CP_WAIT(0); }
        __syncthreads();
        const uint32_t tAh = sb + cur * STAGE_B, tAl = tAh + TILE_B, tBh = tAh + 2 * TILE_B, tBl = tAh + 3 * TILE_B;
        #pragma unroll
        for (int ks = 0; ks < 4; ks++) {
            uint32_t ah[2][4], al[2][4], bh[4][4], bl[4][4];
            #pragma unroll
            for (int mb = 0; mb < 2; mb++) {
                const uint32_t off = swz128((g.a_row + mb * 16) * 128 + g.a_col + ks * 32);
                ldsm_x4(ah[mb], tAh + off);
                ldsm_x4(al[mb], tAl + off);
            }
            #pragma unroll
            for (int nb = 0; nb < 4; nb++) {
                const uint32_t off = swz128((g.b_row + nb * 16) * 128 + g.b_col + ks * 32);
                ldsm_x4(bh[nb], tBh + off);
                ldsm_x4(bl[nb], tBl + off);
            }
            #pragma unroll
            for (int mb = 0; mb < 2; mb++)
                #pragma unroll
                for (int nb = 0; nb < 4; nb++)
                    #pragma unroll
                    for (int h = 0; h < 2; h++) {
                        float* d = g.acc[mb][nb * 2 + h];
                        mma16816(d, ah[mb], &bh[nb][h * 2]);
                        mma16816(d, ah[mb], &bl[nb][h * 2]);
                        mma16816(d, al[mb], &bh[nb][h * 2]);
                    }
        }
        __syncthreads();
    }

    const int er = m0 + g.warp_m * 32 + (g.lane >> 2);
    const int ec = n0 + g.warp_n * 64 + (g.lane & 3) * 2;
    #pragma unroll
    for (int mb = 0; mb < 2; mb++) {
        #pragma unroll
        for (int half = 0; half < 2; half++) {
            const int row = er + mb * 16 + half * 8;
            #pragma unroll
            for (int nb = 0; nb < 8; nb++) {
                const int col = ec + nb * 8;
                float* dst = Cf + (size_t)row * NG + col;
                dst[0] = g.acc[mb][nb][half * 2 + 0] + bias[col];
                dst[1] = g.acc[mb][nb][half * 2 + 1] + bias[col + 1];
            }
        }
    }
}

// ================= HMMA bf16x3 causal flash attention =================
// Grid (T/128, B*H) with qt reversed (longest first); 2 CTAs/SM.
__global__ __launch_bounds__(256, 2)
void attn_mma(const __nv_bfloat16* __restrict__ qh_, const __nv_bfloat16* __restrict__ ql_,
              const __nv_bfloat16* __restrict__ kh_, const __nv_bfloat16* __restrict__ kl_,
              const __nv_bfloat16* __restrict__ vh_, const __nv_bfloat16* __restrict__ vl_,
              __nv_bfloat16* __restrict__ Ohi, __nv_bfloat16* __restrict__ Olo)
{
    extern __shared__ __align__(1024) char smem[];
    const uint32_t sb = smem_u32(smem);
    const int qt = gridDim.x - 1 - blockIdx.x;   // longest-running tiles first
    const int bh = blockIdx.y;
    const int tid = threadIdx.x, wm = tid >> 5, lane = tid & 31;
    const int q0 = qt * 128;
    const size_t gbase = (size_t)bh * TSEQ * HDIM;

    const uint32_t QH = sb, QL = sb + 16384;
    const uint32_t ST = sb + 32768;

    {
        const __nv_bfloat16* s0 = qh_ + gbase + (size_t)q0 * HDIM;
        const __nv_bfloat16* s1 = ql_ + gbase + (size_t)q0 * HDIM;
        #pragma unroll
        for (int i = 0; i < 4; i++) {
            int c = tid + i * 256;
            int row = c >> 3, cc = c & 7;
            uint32_t off = swz128(row * 128 + cc * 16);
            cp_async16(QH + off, s0 + (size_t)row * HDIM + cc * 8);
            cp_async16(QL + off, s1 + (size_t)row * HDIM + cc * 8);
        }
    }
    auto load_kv = [&](int kt, int s) {
        const int k0 = kt * 64;
        const __nv_bfloat16* srcs[4] = {kh_ + gbase + (size_t)k0 * HDIM, kl_ + gbase + (size_t)k0 * HDIM,
                                        vh_ + gbase + (size_t)k0 * HDIM, vl_ + gbase + (size_t)k0 * HDIM};
        #pragma unroll
        for (int t = 0; t < 4; t++) {
            uint32_t dstb = ST + s * 32768 + t * 8192;
            #pragma unroll
            for (int i = 0; i < 2; i++) {
                int c = tid + i * 256;
                int row = c >> 3, cc = c & 7;
                cp_async16(dstb + swz128(row * 128 + cc * 16), srcs[t] + (size_t)row * HDIM + cc * 8);
            }
        }
    };
    load_kv(0, 0);
    CP_COMMIT();

    float m0 = -INFINITY, m1 = -INFINITY, l0 = 0.f, l1 = 0.f;
    float oacc[8][4];
    #pragma unroll
    for (int nb = 0; nb < 8; nb++)
        #pragma unroll
        for (int j = 0; j < 4; j++) oacc[nb][j] = 0.f;

    const int r = lane >> 2, tig = lane & 3;
    const int a_row = wm * 16 + (lane & 7) + ((lane >> 3) & 1) * 8;
    const int a_colb = (lane >> 4) * 16;
    const int b_rowK = (lane & 7) + (lane >> 4) * 8;
    const int b_colbK = ((lane >> 3) & 1) * 16;
    const int v_row = (lane & 7) + ((lane >> 3) & 1) * 8;
    const int v_colb = (lane >> 4) * 16;

    const int nk = 2 * qt + 2;
    for (int kt = 0; kt < nk; kt++) {
        const int cur = kt & 1;
        if (kt + 1 < nk) { load_kv(kt + 1, cur ^ 1); CP_COMMIT(); CP_WAIT(1); }
        else             { CP_WAIT(0); }
        __syncthreads();
        const int k0 = kt * 64;
        const uint32_t KH = ST + cur * 32768, KL = KH + 8192, VH = KH + 16384, VL = KH + 24576;
        const bool active = (k0 <= q0 + wm * 16 + 15);
        if (active) {
            float sacc[8][4];
            #pragma unroll
            for (int nb = 0; nb < 8; nb++)
                #pragma unroll
                for (int j = 0; j < 4; j++) sacc[nb][j] = 0.f;
            #pragma unroll
            for (int ks = 0; ks < 4; ks++) {
                uint32_t ah[4], al[4];
                const uint32_t aoff = swz128(a_row * 128 + a_colb + ks * 32);
                ldsm_x4(ah, QH + aoff);
                ldsm_x4(al, QL + aoff);
                #pragma unroll
                for (int nb16 = 0; nb16 < 4; nb16++) {
                    uint32_t bh4[4], bl4[4];
                    const uint32_t boff = swz128((nb16 * 16 + b_rowK) * 128 + b_colbK + ks * 32);
                    ldsm_x4(bh4, KH + boff);
                    ldsm_x4(bl4, KL + boff);
                    #pragma unroll
                    for (int h = 0; h < 2; h++) {
                        float* d = sacc[nb16 * 2 + h];
                        mma16816(d, ah, &bh4[h * 2]);
                        mma16816(d, ah, &bl4[h * 2]);
                        mma16816(d, al, &bh4[h * 2]);
                    }
                }
            }
            if (k0 + 63 > q0 + wm * 16) {
                #pragma unroll
                for (int nb = 0; nb < 8; nb++)
                    #pragma unroll
                    for (int j = 0; j < 4; j++) {
                        const int qrow = q0 + wm * 16 + r + (j >> 1) * 8;
                        const int kcol = k0 + nb * 8 + tig * 2 + (j & 1);
                        if (kcol > qrow) sacc[nb][j] = -INFINITY;
                    }
            }
            // online softmax in exp2 domain (Q pre-scaled by log2e/8)
            float rx0 = -INFINITY, rx1 = -INFINITY;
            #pragma unroll
            for (int nb = 0; nb < 8; nb++) {
                rx0 = fmaxf(rx0, fmaxf(sacc[nb][0], sacc[nb][1]));
                rx1 = fmaxf(rx1, fmaxf(sacc[nb][2], sacc[nb][3]));
            }
            #pragma unroll
            for (int off = 1; off <= 2; off <<= 1) {
                rx0 = fmaxf(rx0, __shfl_xor_sync(0xffffffffu, rx0, off));
                rx1 = fmaxf(rx1, __shfl_xor_sync(0xffffffffu, rx1, off));
            }
            const float nm0 = fmaxf(m0, rx0), nm1 = fmaxf(m1, rx1);
            const float sc0 = exp2f(m0 - nm0), sc1 = exp2f(m1 - nm1);
            float rs0 = 0.f, rs1 = 0.f;
            #pragma unroll
            for (int nb = 0; nb < 8; nb++) {
                sacc[nb][0] = exp2f(sacc[nb][0] - nm0);
                sacc[nb][1] = exp2f(sacc[nb][1] - nm0);
                sacc[nb][2] = exp2f(sacc[nb][2] - nm1);
                sacc[nb][3] = exp2f(sacc[nb][3] - nm1);
                rs0 += sacc[nb][0] + sacc[nb][1];
                rs1 += sacc[nb][2] + sacc[nb][3];
            }
            #pragma unroll
            for (int off = 1; off <= 2; off <<= 1) {
                rs0 += __shfl_xor_sync(0xffffffffu, rs0, off);
                rs1 += __shfl_xor_sync(0xffffffffu, rs1, off);
            }
            l0 = l0 * sc0 + rs0;
            l1 = l1 * sc1 + rs1;
            m0 = nm0; m1 = nm1;
            #pragma unroll
            for (int nb = 0; nb < 8; nb++) {
                oacc[nb][0] *= sc0; oacc[nb][1] *= sc0;
                oacc[nb][2] *= sc1; oacc[nb][3] *= sc1;
            }
            #pragma unroll
            for (int j = 0; j < 4; j++) {
                uint32_t pah[4], pal[4];
                split_pack(sacc[2 * j][0],     sacc[2 * j][1],     pah[0], pal[0]);
                split_pack(sacc[2 * j][2],     sacc[2 * j][3],     pah[1], pal[1]);
                split_pack(sacc[2 * j + 1][0], sacc[2 * j + 1][1], pah[2], pal[2]);
                split_pack(sacc[2 * j + 1][2], sacc[2 * j + 1][3], pah[3], pal[3]);
                #pragma unroll
                for (int nb16 = 0; nb16 < 4; nb16++) {
                    uint32_t vh4[4], vl4[4];
                    const uint32_t voff = swz128((16 * j + v_row) * 128 + nb16 * 32 + v_colb);
                    ldsm_x4_t(vh4, VH + voff);
                    ldsm_x4_t(vl4, VL + voff);
                    #pragma unroll
                    for (int h = 0; h < 2; h++) {
                        float* d = oacc[nb16 * 2 + h];
                        mma16816(d, pah, &vh4[h * 2]);
                        mma16816(d, pah, &vl4[h * 2]);
                        mma16816(d, pal, &vh4[h * 2]);
                    }
                }
            }
        }
        __syncthreads();
    }

    const float inv0 = 1.0f / l0, inv1 = 1.0f / l1;
    const int b = bh >> 4, h = bh & 15;
    #pragma unroll
    for (int half = 0; half < 2; half++) {
        const int t = q0 + wm * 16 + r + half * 8;
        const float inv = half ? inv1 : inv0;
        const size_t off = ((size_t)(b * TSEQ + t)) * EMBED + h * HDIM;
        #pragma unroll
        for (int nb = 0; nb < 8; nb++) {
            const float v0 = oacc[nb][half * 2 + 0] * inv;
            const float v1 = oacc[nb][half * 2 + 1] * inv;
            uint32_t hi, lo;
            split_pack(v0, v1, hi, lo);
            *(uint32_t*)(Ohi + off + nb * 8 + tig * 2) = hi;
            *(uint32_t*)(Olo + off + nb * 8 + tig * 2) = lo;
        }
    }
}

// ================= launch =================
extern "C" void kernel_launch(void* const* d_in, const int* in_sizes, int n_in,
                              void* d_out, int out_size)
{
    const float* x  = (const float*)d_in[0];
    const float* Wq = (const float*)d_in[1];
    const float* bq = (const float*)d_in[2];
    const float* Wk = (const float*)d_in[3];
    const float* bk = (const float*)d_in[4];
    const float* Wv = (const float*)d_in[5];
    const float* bv = (const float*)d_in[6];
    const float* Wp = (const float*)d_in[7];
    const float* bp = (const float*)d_in[8];
    float* out = (float*)d_out;

    __nv_bfloat16 *qh, *ql, *kh, *kl, *vh, *vl, *ohi, *olo, *xhi, *xlo, *wthi, *wtlo;
    cudaGetSymbolAddress((void**)&qh, g_qh);
    cudaGetSymbolAddress((void**)&ql, g_ql);
    cudaGetSymbolAddress((void**)&kh, g_kh);
    cudaGetSymbolAddress((void**)&kl, g_kl);
    cudaGetSymbolAddress((void**)&vh, g_vh);
    cudaGetSymbolAddress((void**)&vl, g_vl);
    cudaGetSymbolAddress((void**)&ohi, g_ohi);
    cudaGetSymbolAddress((void**)&olo, g_olo);
    cudaGetSymbolAddress((void**)&xhi, g_xhi);
    cudaGetSymbolAddress((void**)&xlo, g_xlo);
    cudaGetSymbolAddress((void**)&wthi, g_wthi);
    cudaGetSymbolAddress((void**)&wtlo, g_wtlo);

    const int gemm_smem = 2 * STAGE_B;
    cudaFuncSetAttribute(qkv_gemm, cudaFuncAttributeMaxDynamicSharedMemorySize, gemm_smem);
    cudaFuncSetAttribute(out_gemm, cudaFuncAttributeMaxDynamicSharedMemorySize, gemm_smem);
    const int attn_smem = 32768 + 2 * 32768;  // 98304
    cudaFuncSetAttribute(attn_mma, cudaFuncAttributeMaxDynamicSharedMemorySize, attn_smem);

    const size_t WN = (size_t)EMBED * EMBED;

    split_f32<<<(MROWS * EMBED / 4 + 255) / 256, 256>>>(x, xhi, xlo, MROWS * EMBED / 4);
    dim3 tgrid(EMBED / 32, EMBED / 32);
    dim3 tblk(32, 8);
    transpose_split<<<tgrid, tblk>>>(Wq, wthi + 0 * WN, wtlo + 0 * WN);
    transpose_split<<<tgrid, tblk>>>(Wk, wthi + 1 * WN, wtlo + 1 * WN);
    transpose_split<<<tgrid, tblk>>>(Wv, wthi + 2 * WN, wtlo + 2 * WN);
    transpose_split<<<tgrid, tblk>>>(Wp, wthi + 3 * WN, wtlo + 3 * WN);

    dim3 qkv_grid(24, MROWS / 128);   // (24, 64)
    qkv_gemm<<<qkv_grid, 256, gemm_smem>>>(xhi, xlo, wthi, wtlo, bq, bk, bv,
                                           qh, ql, kh, kl, vh, vl);

    dim3 agrid(TSEQ / 128, BATCH * HEADS);  // (16, 64)
    attn_mma<<<agrid, 256, attn_smem>>>(qh, ql, kh, kl, vh, vl, ohi, olo);

    dim3 ogrid(EMBED / 128, MROWS / 128);   // (8, 64)
    out_gemm<<<ogrid, 256, gemm_smem>>>(ohi, olo, wthi + 3 * WN, wtlo + 3 * WN, bp, out);

    (void)in_sizes; (void)n_in; (void)out_size;
}

// round 6
// speedup vs baseline: 5.3825x; 1.4446x over previous
#include <cuda_runtime.h>
#include <cuda_fp16.h>
#include <math.h>
#include <stdint.h>

#define EMBED   1024
#define HEADS   16
#define HDIM    64
#define BATCH   4
#define TSEQ    2048
#define MROWS   (BATCH * TSEQ)   // 8192

// ================= helpers =================
__device__ __forceinline__ uint32_t smem_u32(const void* p) {
    uint32_t a;
    asm("{ .reg .u64 t; cvta.to.shared.u64 t, %1; cvt.u32.u64 %0, t; }" : "=r"(a) : "l"(p));
    return a;
}
__device__ __forceinline__ uint32_t swz128(uint32_t off) { return off ^ ((off >> 3) & 0x70); }

__device__ __forceinline__ void cp_async16(uint32_t dst, const void* src) {
    asm volatile("cp.async.cg.shared.global [%0], [%1], 16;" :: "r"(dst), "l"(src));
}
#define CP_COMMIT() asm volatile("cp.async.commit_group;" ::: "memory")
#define CP_WAIT(n)  asm volatile("cp.async.wait_group %0;" :: "n"(n) : "memory")

__device__ __forceinline__ void ldsm_x4(uint32_t* r, uint32_t addr) {
    asm volatile("ldmatrix.sync.aligned.m8n8.x4.shared.b16 {%0,%1,%2,%3}, [%4];"
        : "=r"(r[0]), "=r"(r[1]), "=r"(r[2]), "=r"(r[3]) : "r"(addr));
}
__device__ __forceinline__ void ldsm_x4_t(uint32_t* r, uint32_t addr) {
    asm volatile("ldmatrix.sync.aligned.m8n8.x4.trans.shared.b16 {%0,%1,%2,%3}, [%4];"
        : "=r"(r[0]), "=r"(r[1]), "=r"(r[2]), "=r"(r[3]) : "r"(addr));
}
// fp16 HMMA, f32 accumulate
__device__ __forceinline__ void mma16816h(float* d, const uint32_t* a, const uint32_t* b) {
    asm volatile("mma.sync.aligned.m16n8k16.row.col.f32.f16.f16.f32 "
        "{%0,%1,%2,%3}, {%4,%5,%6,%7}, {%8,%9}, {%0,%1,%2,%3};"
        : "+f"(d[0]), "+f"(d[1]), "+f"(d[2]), "+f"(d[3])
        : "r"(a[0]), "r"(a[1]), "r"(a[2]), "r"(a[3]), "r"(b[0]), "r"(b[1]));
}
// split two floats into fp16-hi pair + fp16-lo(residual) pair, packed u32
__device__ __forceinline__ void split_pack_h(float x, float y, uint32_t& hi, uint32_t& lo) {
    __half hx = __float2half_rn(x), hy = __float2half_rn(y);
    float rx = x - __half2float(hx), ry = y - __half2float(hy);
    __half lx = __float2half_rn(rx), ly = __float2half_rn(ry);
    hi = (uint32_t)__half_as_ushort(hx) | ((uint32_t)__half_as_ushort(hy) << 16);
    lo = (uint32_t)__half_as_ushort(lx) | ((uint32_t)__half_as_ushort(ly) << 16);
}
__device__ __forceinline__ uint32_t pack_h(float x, float y) {
    __half hx = __float2half_rn(x), hy = __float2half_rn(y);
    return (uint32_t)__half_as_ushort(hx) | ((uint32_t)__half_as_ushort(hy) << 16);
}

// ================= scratch =================
__device__ __half g_qh[BATCH * HEADS * TSEQ * HDIM];
__device__ __half g_ql[BATCH * HEADS * TSEQ * HDIM];
__device__ __half g_kh[BATCH * HEADS * TSEQ * HDIM];   // hi only
__device__ __half g_vh[BATCH * HEADS * TSEQ * HDIM];   // hi only
__device__ __half g_ohi[MROWS * EMBED];
__device__ __half g_olo[MROWS * EMBED];
__device__ __half g_xhi[MROWS * EMBED];
__device__ __half g_xlo[MROWS * EMBED];
__device__ __half g_wth[4 * EMBED * EMBED];            // Wt[N,K], hi only

// softmax exp2 fold: Q scaled by 1/8 * log2(e)
#define QSCALE (0.125f * 1.4426950408889634f)

// ================= split conversion (x / o) =================
__global__ __launch_bounds__(256)
void split_f32(const float* __restrict__ in, __half* __restrict__ hi,
               __half* __restrict__ lo, int n4)
{
    int i = blockIdx.x * blockDim.x + threadIdx.x;
    if (i >= n4) return;
    float4 v = ((const float4*)in)[i];
    uint32_t h0, l0, h1, l1;
    split_pack_h(v.x, v.y, h0, l0);
    split_pack_h(v.z, v.w, h1, l1);
    ((uint2*)hi)[i] = make_uint2(h0, h1);
    ((uint2*)lo)[i] = make_uint2(l0, l1);
}

// ================= transpose (W[K,N] -> Wt[N,K], fp16 hi) =================
__global__ __launch_bounds__(256)
void transpose_h(const float* __restrict__ W, __half* __restrict__ hi)
{
    __shared__ float t[32][33];
    const int bx = blockIdx.x * 32;   // N
    const int by = blockIdx.y * 32;   // K
    const int x = threadIdx.x, y = threadIdx.y;  // 32 x 8
    #pragma unroll
    for (int j = 0; j < 32; j += 8)
        t[y + j][x] = W[(size_t)(by + y + j) * EMBED + bx + x];
    __syncthreads();
    #pragma unroll
    for (int j = 0; j < 32; j += 8)
        hi[(size_t)(bx + y + j) * EMBED + by + x] = __float2half_rn(t[x][y + j]);
}

// ================= fp16x2 HMMA GEMM =================
#define TILE_B  16384     // 128 rows x 64 fp16 x 2B
#define STAGE_B 49152     // 3 tiles: Ahi, Alo, Bh

// fused QKV: grid (24, 64). widx = bx>>3 selects weight/output.
__global__ __launch_bounds__(256, 2)
void qkv_gemm(const __half* __restrict__ Ahi, const __half* __restrict__ Alo,
              const __half* __restrict__ Wh,
              const float* __restrict__ bq, const float* __restrict__ bk, const float* __restrict__ bv,
              __half* __restrict__ qh, __half* __restrict__ ql,
              __half* __restrict__ kh, __half* __restrict__ vh)
{
    constexpr int K = EMBED, NK = 16;
    extern __shared__ __align__(1024) char smem[];
    const uint32_t sb = smem_u32(smem);
    const int tid = threadIdx.x, wid = tid >> 5, lane = tid & 31;
    const int widx = blockIdx.x >> 3;
    const int n0 = (blockIdx.x & 7) * 128, m0 = blockIdx.y * 128;
    const size_t WN = (size_t)EMBED * EMBED;

    const __half* Bh = Wh + (size_t)widx * WN;
    const float* bias = (widx == 0) ? bq : (widx == 1) ? bk : bv;
    const float scale = (widx == 0) ? QSCALE : 1.0f;

    const int warp_m = wid & 3, warp_n = wid >> 2;
    float acc[2][8][4];
    #pragma unroll
    for (int mb = 0; mb < 2; mb++)
        #pragma unroll
        for (int nb = 0; nb < 8; nb++)
            #pragma unroll
            for (int j = 0; j < 4; j++) acc[mb][nb][j] = 0.f;

    const int a_row = warp_m * 32 + (lane & 7) + ((lane >> 3) & 1) * 8;
    const int a_col = (lane >> 4) * 16;
    const int b_row = warp_n * 64 + (lane & 7) + (lane >> 4) * 8;
    const int b_col = ((lane >> 3) & 1) * 16;

    const __half* srcs[3] = {Ahi, Alo, Bh};

    auto load_chunk = [&](int kt, int s) {
        #pragma unroll
        for (int t = 0; t < 3; t++) {
            const __half* base = srcs[t] + (size_t)((t < 2) ? m0 : n0) * K + kt * 64;
            const uint32_t tb = sb + s * STAGE_B + t * TILE_B;
            #pragma unroll
            for (int i = 0; i < 4; i++) {
                int chunk = tid + i * 256;
                int r = chunk >> 3, c = chunk & 7;
                cp_async16(tb + swz128(r * 128 + c * 16), base + (size_t)r * K + c * 8);
            }
        }
        CP_COMMIT();
    };

    load_chunk(0, 0);
    for (int kt = 0; kt < NK; kt++) {
        const int cur = kt & 1;
        if (kt + 1 < NK) { load_chunk(kt + 1, cur ^ 1); CP_WAIT(1); }
        else             { CP_WAIT(0); }
        __syncthreads();
        const uint32_t tAh = sb + cur * STAGE_B, tAl = tAh + TILE_B, tBh = tAh + 2 * TILE_B;
        #pragma unroll
        for (int ks = 0; ks < 4; ks++) {
            uint32_t ah[2][4], al[2][4], bh4[4][4];
            #pragma unroll
            for (int mb = 0; mb < 2; mb++) {
                const uint32_t off = swz128((a_row + mb * 16) * 128 + a_col + ks * 32);
                ldsm_x4(ah[mb], tAh + off);
                ldsm_x4(al[mb], tAl + off);
            }
            #pragma unroll
            for (int nb = 0; nb < 4; nb++) {
                const uint32_t off = swz128((b_row + nb * 16) * 128 + b_col + ks * 32);
                ldsm_x4(bh4[nb], tBh + off);
            }
            #pragma unroll
            for (int mb = 0; mb < 2; mb++)
                #pragma unroll
                for (int nb = 0; nb < 4; nb++)
                    #pragma unroll
                    for (int h = 0; h < 2; h++) {
                        float* d = acc[mb][nb * 2 + h];
                        mma16816h(d, ah[mb], &bh4[nb][h * 2]);
                        mma16816h(d, al[mb], &bh4[nb][h * 2]);
                    }
        }
        __syncthreads();
    }

    const int er = m0 + warp_m * 32 + (lane >> 2);
    const int ec = n0 + warp_n * 64 + (lane & 3) * 2;
    #pragma unroll
    for (int mb = 0; mb < 2; mb++) {
        #pragma unroll
        for (int half = 0; half < 2; half++) {
            const int row = er + mb * 16 + half * 8;
            const int b = row / TSEQ, t = row % TSEQ;
            #pragma unroll
            for (int nb = 0; nb < 8; nb++) {
                const int col = ec + nb * 8;
                const float v0 = (acc[mb][nb][half * 2 + 0] + bias[col]) * scale;
                const float v1 = (acc[mb][nb][half * 2 + 1] + bias[col + 1]) * scale;
                const int hh = col >> 6, dd = col & 63;
                const size_t idx = (((size_t)(b * HEADS + hh)) * TSEQ + t) * HDIM + dd;
                if (widx == 0) {
                    uint32_t hi, lo;
                    split_pack_h(v0, v1, hi, lo);
                    *(uint32_t*)(qh + idx) = hi;
                    *(uint32_t*)(ql + idx) = lo;
                } else {
                    __half* dst = (widx == 1) ? kh : vh;
                    *(uint32_t*)(dst + idx) = pack_h(v0, v1);
                }
            }
        }
    }
}

// out-projection: f32 output [M,N]
__global__ __launch_bounds__(256, 2)
void out_gemm(const __half* __restrict__ Ahi, const __half* __restrict__ Alo,
              const __half* __restrict__ Bh,
              const float* __restrict__ bias, float* __restrict__ Cf)
{
    constexpr int K = EMBED, NG = EMBED, NK = 16;
    extern __shared__ __align__(1024) char smem[];
    const uint32_t sb = smem_u32(smem);
    const int tid = threadIdx.x, wid = tid >> 5, lane = tid & 31;
    const int n0 = blockIdx.x * 128, m0 = blockIdx.y * 128;

    const int warp_m = wid & 3, warp_n = wid >> 2;
    float acc[2][8][4];
    #pragma unroll
    for (int mb = 0; mb < 2; mb++)
        #pragma unroll
        for (int nb = 0; nb < 8; nb++)
            #pragma unroll
            for (int j = 0; j < 4; j++) acc[mb][nb][j] = 0.f;

    const int a_row = warp_m * 32 + (lane & 7) + ((lane >> 3) & 1) * 8;
    const int a_col = (lane >> 4) * 16;
    const int b_row = warp_n * 64 + (lane & 7) + (lane >> 4) * 8;
    const int b_col = ((lane >> 3) & 1) * 16;

    const __half* srcs[3] = {Ahi, Alo, Bh};

    auto load_chunk = [&](int kt, int s) {
        #pragma unroll
        for (int t = 0; t < 3; t++) {
            const __half* base = srcs[t] + (size_t)((t < 2) ? m0 : n0) * K + kt * 64;
            const uint32_t tb = sb + s * STAGE_B + t * TILE_B;
            #pragma unroll
            for (int i = 0; i < 4; i++) {
                int chunk = tid + i * 256;
                int r = chunk >> 3, c = chunk & 7;
                cp_async16(tb + swz128(r * 128 + c * 16), base + (size_t)r * K + c * 8);
            }
        }
        CP_COMMIT();
    };

    load_chunk(0, 0);
    for (int kt = 0; kt < NK; kt++) {
        const int cur = kt & 1;
        if (kt + 1 < NK) { load_chunk(kt + 1, cur ^ 1); CP_WAIT(1); }
        else             { CP_WAIT(0); }
        __syncthreads();
        const uint32_t tAh = sb + cur * STAGE_B, tAl = tAh + TILE_B, tBh = tAh + 2 * TILE_B;
        #pragma unroll
        for (int ks = 0; ks < 4; ks++) {
            uint32_t ah[2][4], al[2][4], bh4[4][4];
            #pragma unroll
            for (int mb = 0; mb < 2; mb++) {
                const uint32_t off = swz128((a_row + mb * 16) * 128 + a_col + ks * 32);
                ldsm_x4(ah[mb], tAh + off);
                ldsm_x4(al[mb], tAl + off);
            }
            #pragma unroll
            for (int nb = 0; nb < 4; nb++) {
                const uint32_t off = swz128((b_row + nb * 16) * 128 + b_col + ks * 32);
                ldsm_x4(bh4[nb], tBh + off);
            }
            #pragma unroll
            for (int mb = 0; mb < 2; mb++)
                #pragma unroll
                for (int nb = 0; nb < 4; nb++)
                    #pragma unroll
                    for (int h = 0; h < 2; h++) {
                        float* d = acc[mb][nb * 2 + h];
                        mma16816h(d, ah[mb], &bh4[nb][h * 2]);
                        mma16816h(d, al[mb], &bh4[nb][h * 2]);
                    }
        }
        __syncthreads();
    }

    const int er = m0 + warp_m * 32 + (lane >> 2);
    const int ec = n0 + warp_n * 64 + (lane & 3) * 2;
    #pragma unroll
    for (int mb = 0; mb < 2; mb++) {
        #pragma unroll
        for (int half = 0; half < 2; half++) {
            const int row = er + mb * 16 + half * 8;
            #pragma unroll
            for (int nb = 0; nb < 8; nb++) {
                const int col = ec + nb * 8;
                float* dst = Cf + (size_t)row * NG + col;
                dst[0] = acc[mb][nb][half * 2 + 0] + bias[col];
                dst[1] = acc[mb][nb][half * 2 + 1] + bias[col + 1];
            }
        }
    }
}

// ================= fp16x2 HMMA causal flash attention =================
// Grid (T/128, B*H) with qt reversed; 2 CTAs/SM (64 KB smem).
__global__ __launch_bounds__(256, 2)
void attn_mma(const __half* __restrict__ qh_, const __half* __restrict__ ql_,
              const __half* __restrict__ kh_, const __half* __restrict__ vh_,
              __half* __restrict__ Ohi, __half* __restrict__ Olo)
{
    extern __shared__ __align__(1024) char smem[];
    const uint32_t sb = smem_u32(smem);
    const int qt = gridDim.x - 1 - blockIdx.x;   // longest tiles first
    const int bh = blockIdx.y;
    const int tid = threadIdx.x, wm = tid >> 5, lane = tid & 31;
    const int q0 = qt * 128;
    const size_t gbase = (size_t)bh * TSEQ * HDIM;

    const uint32_t QH = sb, QL = sb + 16384;
    const uint32_t ST = sb + 32768;   // per stage: KH(8K) VH(8K); 2 stages

    {
        const __half* s0 = qh_ + gbase + (size_t)q0 * HDIM;
        const __half* s1 = ql_ + gbase + (size_t)q0 * HDIM;
        #pragma unroll
        for (int i = 0; i < 4; i++) {
            int c = tid + i * 256;
            int row = c >> 3, cc = c & 7;
            uint32_t off = swz128(row * 128 + cc * 16);
            cp_async16(QH + off, s0 + (size_t)row * HDIM + cc * 8);
            cp_async16(QL + off, s1 + (size_t)row * HDIM + cc * 8);
        }
    }
    auto load_kv = [&](int kt, int s) {
        const int k0 = kt * 64;
        const __half* srcs[2] = {kh_ + gbase + (size_t)k0 * HDIM, vh_ + gbase + (size_t)k0 * HDIM};
        #pragma unroll
        for (int t = 0; t < 2; t++) {
            uint32_t dstb = ST + s * 16384 + t * 8192;
            #pragma unroll
            for (int i = 0; i < 2; i++) {
                int c = tid + i * 256;
                int row = c >> 3, cc = c & 7;
                cp_async16(dstb + swz128(row * 128 + cc * 16), srcs[t] + (size_t)row * HDIM + cc * 8);
            }
        }
    };
    load_kv(0, 0);
    CP_COMMIT();

    float m0 = -INFINITY, m1 = -INFINITY, l0 = 0.f, l1 = 0.f;
    float oacc[8][4];
    #pragma unroll
    for (int nb = 0; nb < 8; nb++)
        #pragma unroll
        for (int j = 0; j < 4; j++) oacc[nb][j] = 0.f;

    const int r = lane >> 2, tig = lane & 3;
    const int a_row = wm * 16 + (lane & 7) + ((lane >> 3) & 1) * 8;
    const int a_colb = (lane >> 4) * 16;
    const int b_rowK = (lane & 7) + (lane >> 4) * 8;
    const int b_colbK = ((lane >> 3) & 1) * 16;
    const int v_row = (lane & 7) + ((lane >> 3) & 1) * 8;
    const int v_colb = (lane >> 4) * 16;

    const int nk = 2 * qt + 2;
    for (int kt = 0; kt < nk; kt++) {
        const int cur = kt & 1;
        if (kt + 1 < nk) { load_kv(kt + 1, cur ^ 1); CP_COMMIT(); CP_WAIT(1); }
        else             { CP_WAIT(0); }
        __syncthreads();
        const int k0 = kt * 64;
        const uint32_t KH = ST + cur * 16384, VH = KH + 8192;
        const bool active = (k0 <= q0 + wm * 16 + 15);
        if (active) {
            float sacc[8][4];
            #pragma unroll
            for (int nb = 0; nb < 8; nb++)
                #pragma unroll
                for (int j = 0; j < 4; j++) sacc[nb][j] = 0.f;
            #pragma unroll
            for (int ks = 0; ks < 4; ks++) {
                uint32_t ah[4], al[4];
                const uint32_t aoff = swz128(a_row * 128 + a_colb + ks * 32);
                ldsm_x4(ah, QH + aoff);
                ldsm_x4(al, QL + aoff);
                #pragma unroll
                for (int nb16 = 0; nb16 < 4; nb16++) {
                    uint32_t bh4[4];
                    const uint32_t boff = swz128((nb16 * 16 + b_rowK) * 128 + b_colbK + ks * 32);
                    ldsm_x4(bh4, KH + boff);
                    #pragma unroll
                    for (int h = 0; h < 2; h++) {
                        float* d = sacc[nb16 * 2 + h];
                        mma16816h(d, ah, &bh4[h * 2]);
                        mma16816h(d, al, &bh4[h * 2]);
                    }
                }
            }
            if (k0 + 63 > q0 + wm * 16) {
                #pragma unroll
                for (int nb = 0; nb < 8; nb++)
                    #pragma unroll
                    for (int j = 0; j < 4; j++) {
                        const int qrow = q0 + wm * 16 + r + (j >> 1) * 8;
                        const int kcol = k0 + nb * 8 + tig * 2 + (j & 1);
                        if (kcol > qrow) sacc[nb][j] = -INFINITY;
                    }
            }
            // online softmax, exp2 domain
            float rx0 = -INFINITY, rx1 = -INFINITY;
            #pragma unroll
            for (int nb = 0; nb < 8; nb++) {
                rx0 = fmaxf(rx0, fmaxf(sacc[nb][0], sacc[nb][1]));
                rx1 = fmaxf(rx1, fmaxf(sacc[nb][2], sacc[nb][3]));
            }
            #pragma unroll
            for (int off = 1; off <= 2; off <<= 1) {
                rx0 = fmaxf(rx0, __shfl_xor_sync(0xffffffffu, rx0, off));
                rx1 = fmaxf(rx1, __shfl_xor_sync(0xffffffffu, rx1, off));
            }
            const float nm0 = fmaxf(m0, rx0), nm1 = fmaxf(m1, rx1);
            const float sc0 = exp2f(m0 - nm0), sc1 = exp2f(m1 - nm1);
            float rs0 = 0.f, rs1 = 0.f;
            #pragma unroll
            for (int nb = 0; nb < 8; nb++) {
                sacc[nb][0] = exp2f(sacc[nb][0] - nm0);
                sacc[nb][1] = exp2f(sacc[nb][1] - nm0);
                sacc[nb][2] = exp2f(sacc[nb][2] - nm1);
                sacc[nb][3] = exp2f(sacc[nb][3] - nm1);
                rs0 += sacc[nb][0] + sacc[nb][1];
                rs1 += sacc[nb][2] + sacc[nb][3];
            }
            #pragma unroll
            for (int off = 1; off <= 2; off <<= 1) {
                rs0 += __shfl_xor_sync(0xffffffffu, rs0, off);
                rs1 += __shfl_xor_sync(0xffffffffu, rs1, off);
            }
            l0 = l0 * sc0 + rs0;
            l1 = l1 * sc1 + rs1;
            m0 = nm0; m1 = nm1;
            #pragma unroll
            for (int nb = 0; nb < 8; nb++) {
                oacc[nb][0] *= sc0; oacc[nb][1] *= sc0;
                oacc[nb][2] *= sc1; oacc[nb][3] *= sc1;
            }
            // O += P V, P split hi/lo fp16, V hi-only
            #pragma unroll
            for (int j = 0; j < 4; j++) {
                uint32_t pah[4], pal[4];
                split_pack_h(sacc[2 * j][0],     sacc[2 * j][1],     pah[0], pal[0]);
                split_pack_h(sacc[2 * j][2],     sacc[2 * j][3],     pah[1], pal[1]);
                split_pack_h(sacc[2 * j + 1][0], sacc[2 * j + 1][1], pah[2], pal[2]);
                split_pack_h(sacc[2 * j + 1][2], sacc[2 * j + 1][3], pah[3], pal[3]);
                #pragma unroll
                for (int nb16 = 0; nb16 < 4; nb16++) {
                    uint32_t vh4[4];
                    const uint32_t voff = swz128((16 * j + v_row) * 128 + nb16 * 32 + v_colb);
                    ldsm_x4_t(vh4, VH + voff);
                    #pragma unroll
                    for (int h = 0; h < 2; h++) {
                        float* d = oacc[nb16 * 2 + h];
                        mma16816h(d, pah, &vh4[h * 2]);
                        mma16816h(d, pal, &vh4[h * 2]);
                    }
                }
            }
        }
        __syncthreads();
    }

    const float inv0 = 1.0f / l0, inv1 = 1.0f / l1;
    const int b = bh >> 4, h = bh & 15;
    #pragma unroll
    for (int half = 0; half < 2; half++) {
        const int t = q0 + wm * 16 + r + half * 8;
        const float inv = half ? inv1 : inv0;
        const size_t off = ((size_t)(b * TSEQ + t)) * EMBED + h * HDIM;
        #pragma unroll
        for (int nb = 0; nb < 8; nb++) {
            const float v0 = oacc[nb][half * 2 + 0] * inv;
            const float v1 = oacc[nb][half * 2 + 1] * inv;
            uint32_t hi, lo;
            split_pack_h(v0, v1, hi, lo);
            *(uint32_t*)(Ohi + off + nb * 8 + tig * 2) = hi;
            *(uint32_t*)(Olo + off + nb * 8 + tig * 2) = lo;
        }
    }
}

// ================= launch =================
extern "C" void kernel_launch(void* const* d_in, const int* in_sizes, int n_in,
                              void* d_out, int out_size)
{
    const float* x  = (const float*)d_in[0];
    const float* Wq = (const float*)d_in[1];
    const float* bq = (const float*)d_in[2];
    const float* Wk = (const float*)d_in[3];
    const float* bk = (const float*)d_in[4];
    const float* Wv = (const float*)d_in[5];
    const float* bv = (const float*)d_in[6];
    const float* Wp = (const float*)d_in[7];
    const float* bp = (const float*)d_in[8];
    float* out = (float*)d_out;

    __half *qh, *ql, *kh, *vh, *ohi, *olo, *xhi, *xlo, *wth;
    cudaGetSymbolAddress((void**)&qh, g_qh);
    cudaGetSymbolAddress((void**)&ql, g_ql);
    cudaGetSymbolAddress((void**)&kh, g_kh);
    cudaGetSymbolAddress((void**)&vh, g_vh);
    cudaGetSymbolAddress((void**)&ohi, g_ohi);
    cudaGetSymbolAddress((void**)&olo, g_olo);
    cudaGetSymbolAddress((void**)&xhi, g_xhi);
    cudaGetSymbolAddress((void**)&xlo, g_xlo);
    cudaGetSymbolAddress((void**)&wth, g_wth);

    const int gemm_smem = 2 * STAGE_B;   // 98304
    cudaFuncSetAttribute(qkv_gemm, cudaFuncAttributeMaxDynamicSharedMemorySize, gemm_smem);
    cudaFuncSetAttribute(out_gemm, cudaFuncAttributeMaxDynamicSharedMemorySize, gemm_smem);
    const int attn_smem = 65536;
    cudaFuncSetAttribute(attn_mma, cudaFuncAttributeMaxDynamicSharedMemorySize, attn_smem);

    const size_t WN = (size_t)EMBED * EMBED;

    split_f32<<<(MROWS * EMBED / 4 + 255) / 256, 256>>>(x, xhi, xlo, MROWS * EMBED / 4);
    dim3 tgrid(EMBED / 32, EMBED / 32);
    dim3 tblk(32, 8);
    transpose_h<<<tgrid, tblk>>>(Wq, wth + 0 * WN);
    transpose_h<<<tgrid, tblk>>>(Wk, wth + 1 * WN);
    transpose_h<<<tgrid, tblk>>>(Wv, wth + 2 * WN);
    transpose_h<<<tgrid, tblk>>>(Wp, wth + 3 * WN);

    dim3 qkv_grid(24, MROWS / 128);   // (24, 64)
    qkv_gemm<<<qkv_grid, 256, gemm_smem>>>(xhi, xlo, wth, bq, bk, bv, qh, ql, kh, vh);

    dim3 agrid(TSEQ / 128, BATCH * HEADS);  // (16, 64)
    attn_mma<<<agrid, 256, attn_smem>>>(qh, ql, kh, vh, ohi, olo);

    dim3 ogrid(EMBED / 128, MROWS / 128);   // (8, 64)
    out_gemm<<<ogrid, 256, gemm_smem>>>(ohi, olo, wth + 3 * WN, bp, out);

    (void)in_sizes; (void)n_in; (void)out_size;
}

// round 7
// speedup vs baseline: 5.8621x; 1.0891x over previous
#include <cuda_runtime.h>
#include <cuda_fp16.h>
#include <math.h>
#include <stdint.h>

#define EMBED   1024
#define HEADS   16
#define HDIM    64
#define BATCH   4
#define TSEQ    2048
#define MROWS   (BATCH * TSEQ)   // 8192

// ================= helpers =================
__device__ __forceinline__ uint32_t smem_u32(const void* p) {
    uint32_t a;
    asm("{ .reg .u64 t; cvta.to.shared.u64 t, %1; cvt.u32.u64 %0, t; }" : "=r"(a) : "l"(p));
    return a;
}
__device__ __forceinline__ uint32_t swz128(uint32_t off) { return off ^ ((off >> 3) & 0x70); }

__device__ __forceinline__ void cp_async16(uint32_t dst, const void* src) {
    asm volatile("cp.async.cg.shared.global [%0], [%1], 16;" :: "r"(dst), "l"(src));
}
#define CP_COMMIT() asm volatile("cp.async.commit_group;" ::: "memory")
#define CP_WAIT(n)  asm volatile("cp.async.wait_group %0;" :: "n"(n) : "memory")

__device__ __forceinline__ void ldsm_x4(uint32_t* r, uint32_t addr) {
    asm volatile("ldmatrix.sync.aligned.m8n8.x4.shared.b16 {%0,%1,%2,%3}, [%4];"
        : "=r"(r[0]), "=r"(r[1]), "=r"(r[2]), "=r"(r[3]) : "r"(addr));
}
__device__ __forceinline__ void ldsm_x4_t(uint32_t* r, uint32_t addr) {
    asm volatile("ldmatrix.sync.aligned.m8n8.x4.trans.shared.b16 {%0,%1,%2,%3}, [%4];"
        : "=r"(r[0]), "=r"(r[1]), "=r"(r[2]), "=r"(r[3]) : "r"(addr));
}
__device__ __forceinline__ void mma16816h(float* d, const uint32_t* a, const uint32_t* b) {
    asm volatile("mma.sync.aligned.m16n8k16.row.col.f32.f16.f16.f32 "
        "{%0,%1,%2,%3}, {%4,%5,%6,%7}, {%8,%9}, {%0,%1,%2,%3};"
        : "+f"(d[0]), "+f"(d[1]), "+f"(d[2]), "+f"(d[3])
        : "r"(a[0]), "r"(a[1]), "r"(a[2]), "r"(a[3]), "r"(b[0]), "r"(b[1]));
}
__device__ __forceinline__ void split_pack_h(float x, float y, uint32_t& hi, uint32_t& lo) {
    __half hx = __float2half_rn(x), hy = __float2half_rn(y);
    float rx = x - __half2float(hx), ry = y - __half2float(hy);
    __half lx = __float2half_rn(rx), ly = __float2half_rn(ry);
    hi = (uint32_t)__half_as_ushort(hx) | ((uint32_t)__half_as_ushort(hy) << 16);
    lo = (uint32_t)__half_as_ushort(lx) | ((uint32_t)__half_as_ushort(ly) << 16);
}
__device__ __forceinline__ uint32_t pack_h(float x, float y) {
    __half hx = __float2half_rn(x), hy = __float2half_rn(y);
    return (uint32_t)__half_as_ushort(hx) | ((uint32_t)__half_as_ushort(hy) << 16);
}

// ================= scratch =================
__device__ __half g_qh[BATCH * HEADS * TSEQ * HDIM];
__device__ __half g_ql[BATCH * HEADS * TSEQ * HDIM];
__device__ __half g_kh[BATCH * HEADS * TSEQ * HDIM];   // hi only
__device__ __half g_vh[BATCH * HEADS * TSEQ * HDIM];   // hi only
__device__ __half g_ohi[MROWS * EMBED];                // hi only (single-term out proj)
__device__ __half g_xhi[MROWS * EMBED];
__device__ __half g_xlo[MROWS * EMBED];
__device__ __half g_wth[4 * EMBED * EMBED];            // Wt[N,K], hi only

// softmax exp2 fold: Q scaled by 1/8 * log2(e)
#define QSCALE (0.125f * 1.4426950408889634f)

// ================= split conversion (x) =================
__global__ __launch_bounds__(256)
void split_f32(const float* __restrict__ in, __half* __restrict__ hi,
               __half* __restrict__ lo, int n4)
{
    int i = blockIdx.x * blockDim.x + threadIdx.x;
    if (i >= n4) return;
    float4 v = ((const float4*)in)[i];
    uint32_t h0, l0, h1, l1;
    split_pack_h(v.x, v.y, h0, l0);
    split_pack_h(v.z, v.w, h1, l1);
    ((uint2*)hi)[i] = make_uint2(h0, h1);
    ((uint2*)lo)[i] = make_uint2(l0, l1);
}

// ================= transpose all 4 weights (z = weight idx) =================
__global__ __launch_bounds__(256)
void transpose_h4(const float* __restrict__ W0, const float* __restrict__ W1,
                  const float* __restrict__ W2, const float* __restrict__ W3,
                  __half* __restrict__ hi)
{
    __shared__ float t[32][33];
    const int z = blockIdx.z;
    const float* W = (z == 0) ? W0 : (z == 1) ? W1 : (z == 2) ? W2 : W3;
    __half* dst = hi + (size_t)z * EMBED * EMBED;
    const int bx = blockIdx.x * 32;   // N
    const int by = blockIdx.y * 32;   // K
    const int x = threadIdx.x, y = threadIdx.y;  // 32 x 8
    #pragma unroll
    for (int j = 0; j < 32; j += 8)
        t[y + j][x] = W[(size_t)(by + y + j) * EMBED + bx + x];
    __syncthreads();
    #pragma unroll
    for (int j = 0; j < 32; j += 8)
        dst[(size_t)(bx + y + j) * EMBED + by + x] = __float2half_rn(t[x][y + j]);
}

// ================= fp16x2 HMMA GEMM =================
#define TILE_B  16384     // 128 rows x 64 fp16 x 2B
#define STAGE_B 49152     // 3 tiles: Ahi, Alo, Bh

// fused QKV: grid (24, 64). widx = bx>>3 selects weight/output.
__global__ __launch_bounds__(256, 2)
void qkv_gemm(const __half* __restrict__ Ahi, const __half* __restrict__ Alo,
              const __half* __restrict__ Wh,
              const float* __restrict__ bq, const float* __restrict__ bk, const float* __restrict__ bv,
              __half* __restrict__ qh, __half* __restrict__ ql,
              __half* __restrict__ kh, __half* __restrict__ vh)
{
    constexpr int K = EMBED, NK = 16;
    extern __shared__ __align__(1024) char smem[];
    const uint32_t sb = smem_u32(smem);
    const int tid = threadIdx.x, wid = tid >> 5, lane = tid & 31;
    const int widx = blockIdx.x >> 3;
    const int n0 = (blockIdx.x & 7) * 128, m0 = blockIdx.y * 128;
    const size_t WN = (size_t)EMBED * EMBED;

    const __half* Bh = Wh + (size_t)widx * WN;
    const float* bias = (widx == 0) ? bq : (widx == 1) ? bk : bv;
    const float scale = (widx == 0) ? QSCALE : 1.0f;

    const int warp_m = wid & 3, warp_n = wid >> 2;
    float acc[2][8][4];
    #pragma unroll
    for (int mb = 0; mb < 2; mb++)
        #pragma unroll
        for (int nb = 0; nb < 8; nb++)
            #pragma unroll
            for (int j = 0; j < 4; j++) acc[mb][nb][j] = 0.f;

    const int a_row = warp_m * 32 + (lane & 7) + ((lane >> 3) & 1) * 8;
    const int a_col = (lane >> 4) * 16;
    const int b_row = warp_n * 64 + (lane & 7) + (lane >> 4) * 8;
    const int b_col = ((lane >> 3) & 1) * 16;

    const __half* srcs[3] = {Ahi, Alo, Bh};

    auto load_chunk = [&](int kt, int s) {
        #pragma unroll
        for (int t = 0; t < 3; t++) {
            const __half* base = srcs[t] + (size_t)((t < 2) ? m0 : n0) * K + kt * 64;
            const uint32_t tb = sb + s * STAGE_B + t * TILE_B;
            #pragma unroll
            for (int i = 0; i < 4; i++) {
                int chunk = tid + i * 256;
                int r = chunk >> 3, c = chunk & 7;
                cp_async16(tb + swz128(r * 128 + c * 16), base + (size_t)r * K + c * 8);
            }
        }
        CP_COMMIT();
    };

    load_chunk(0, 0);
    for (int kt = 0; kt < NK; kt++) {
        const int cur = kt & 1;
        if (kt + 1 < NK) { load_chunk(kt + 1, cur ^ 1); CP_WAIT(1); }
        else             { CP_WAIT(0); }
        __syncthreads();
        const uint32_t tAh = sb + cur * STAGE_B, tAl = tAh + TILE_B, tBh = tAh + 2 * TILE_B;
        #pragma unroll
        for (int ks = 0; ks < 4; ks++) {
            uint32_t ah[2][4], al[2][4], bh4[4][4];
            #pragma unroll
            for (int mb = 0; mb < 2; mb++) {
                const uint32_t off = swz128((a_row + mb * 16) * 128 + a_col + ks * 32);
                ldsm_x4(ah[mb], tAh + off);
                ldsm_x4(al[mb], tAl + off);
            }
            #pragma unroll
            for (int nb = 0; nb < 4; nb++) {
                const uint32_t off = swz128((b_row + nb * 16) * 128 + b_col + ks * 32);
                ldsm_x4(bh4[nb], tBh + off);
            }
            #pragma unroll
            for (int mb = 0; mb < 2; mb++)
                #pragma unroll
                for (int nb = 0; nb < 4; nb++)
                    #pragma unroll
                    for (int h = 0; h < 2; h++) {
                        float* d = acc[mb][nb * 2 + h];
                        mma16816h(d, ah[mb], &bh4[nb][h * 2]);
                        mma16816h(d, al[mb], &bh4[nb][h * 2]);
                    }
        }
        __syncthreads();
    }

    const int er = m0 + warp_m * 32 + (lane >> 2);
    const int ec = n0 + warp_n * 64 + (lane & 3) * 2;
    #pragma unroll
    for (int mb = 0; mb < 2; mb++) {
        #pragma unroll
        for (int half = 0; half < 2; half++) {
            const int row = er + mb * 16 + half * 8;
            const int b = row / TSEQ, t = row % TSEQ;
            #pragma unroll
            for (int nb = 0; nb < 8; nb++) {
                const int col = ec + nb * 8;
                const float v0 = (acc[mb][nb][half * 2 + 0] + bias[col]) * scale;
                const float v1 = (acc[mb][nb][half * 2 + 1] + bias[col + 1]) * scale;
                const int hh = col >> 6, dd = col & 63;
                const size_t idx = (((size_t)(b * HEADS + hh)) * TSEQ + t) * HDIM + dd;
                if (widx == 0) {
                    uint32_t hi, lo;
                    split_pack_h(v0, v1, hi, lo);
                    *(uint32_t*)(qh + idx) = hi;
                    *(uint32_t*)(ql + idx) = lo;
                } else {
                    __half* dst = (widx == 1) ? kh : vh;
                    *(uint32_t*)(dst + idx) = pack_h(v0, v1);
                }
            }
        }
    }
}

// out-projection: single fp16 A term, f32 output [M,N]
#define OSTAGE_B 32768    // 2 tiles: Ah, Bh
__global__ __launch_bounds__(256, 2)
void out_gemm(const __half* __restrict__ Ah_, const __half* __restrict__ Bh_,
              const float* __restrict__ bias, float* __restrict__ Cf)
{
    constexpr int K = EMBED, NG = EMBED, NK = 16;
    extern __shared__ __align__(1024) char smem[];
    const uint32_t sb = smem_u32(smem);
    const int tid = threadIdx.x, wid = tid >> 5, lane = tid & 31;
    const int n0 = blockIdx.x * 128, m0 = blockIdx.y * 128;

    const int warp_m = wid & 3, warp_n = wid >> 2;
    float acc[2][8][4];
    #pragma unroll
    for (int mb = 0; mb < 2; mb++)
        #pragma unroll
        for (int nb = 0; nb < 8; nb++)
            #pragma unroll
            for (int j = 0; j < 4; j++) acc[mb][nb][j] = 0.f;

    const int a_row = warp_m * 32 + (lane & 7) + ((lane >> 3) & 1) * 8;
    const int a_col = (lane >> 4) * 16;
    const int b_row = warp_n * 64 + (lane & 7) + (lane >> 4) * 8;
    const int b_col = ((lane >> 3) & 1) * 16;

    const __half* srcs[2] = {Ah_, Bh_};

    auto load_chunk = [&](int kt, int s) {
        #pragma unroll
        for (int t = 0; t < 2; t++) {
            const __half* base = srcs[t] + (size_t)((t == 0) ? m0 : n0) * K + kt * 64;
            const uint32_t tb = sb + s * OSTAGE_B + t * TILE_B;
            #pragma unroll
            for (int i = 0; i < 4; i++) {
                int chunk = tid + i * 256;
                int r = chunk >> 3, c = chunk & 7;
                cp_async16(tb + swz128(r * 128 + c * 16), base + (size_t)r * K + c * 8);
            }
        }
        CP_COMMIT();
    };

    load_chunk(0, 0);
    for (int kt = 0; kt < NK; kt++) {
        const int cur = kt & 1;
        if (kt + 1 < NK) { load_chunk(kt + 1, cur ^ 1); CP_WAIT(1); }
        else             { CP_WAIT(0); }
        __syncthreads();
        const uint32_t tAh = sb + cur * OSTAGE_B, tBh = tAh + TILE_B;
        #pragma unroll
        for (int ks = 0; ks < 4; ks++) {
            uint32_t ah[2][4], bh4[4][4];
            #pragma unroll
            for (int mb = 0; mb < 2; mb++)
                ldsm_x4(ah[mb], tAh + swz128((a_row + mb * 16) * 128 + a_col + ks * 32));
            #pragma unroll
            for (int nb = 0; nb < 4; nb++)
                ldsm_x4(bh4[nb], tBh + swz128((b_row + nb * 16) * 128 + b_col + ks * 32));
            #pragma unroll
            for (int mb = 0; mb < 2; mb++)
                #pragma unroll
                for (int nb = 0; nb < 4; nb++)
                    #pragma unroll
                    for (int h = 0; h < 2; h++)
                        mma16816h(acc[mb][nb * 2 + h], ah[mb], &bh4[nb][h * 2]);
        }
        __syncthreads();
    }

    const int er = m0 + warp_m * 32 + (lane >> 2);
    const int ec = n0 + warp_n * 64 + (lane & 3) * 2;
    #pragma unroll
    for (int mb = 0; mb < 2; mb++) {
        #pragma unroll
        for (int half = 0; half < 2; half++) {
            const int row = er + mb * 16 + half * 8;
            #pragma unroll
            for (int nb = 0; nb < 8; nb++) {
                const int col = ec + nb * 8;
                float* dst = Cf + (size_t)row * NG + col;
                dst[0] = acc[mb][nb][half * 2 + 0] + bias[col];
                dst[1] = acc[mb][nb][half * 2 + 1] + bias[col + 1];
            }
        }
    }
}

// ================= fp16x2 HMMA causal flash attention =================
__global__ __launch_bounds__(256, 2)
void attn_mma(const __half* __restrict__ qh_, const __half* __restrict__ ql_,
              const __half* __restrict__ kh_, const __half* __restrict__ vh_,
              __half* __restrict__ Ohi)
{
    extern __shared__ __align__(1024) char smem[];
    const uint32_t sb = smem_u32(smem);
    const int qt = gridDim.x - 1 - blockIdx.x;   // longest tiles first
    const int bh = blockIdx.y;
    const int tid = threadIdx.x, wm = tid >> 5, lane = tid & 31;
    const int q0 = qt * 128;
    const size_t gbase = (size_t)bh * TSEQ * HDIM;

    const uint32_t QH = sb, QL = sb + 16384;
    const uint32_t ST = sb + 32768;   // per stage: KH(8K) VH(8K); 2 stages

    {
        const __half* s0 = qh_ + gbase + (size_t)q0 * HDIM;
        const __half* s1 = ql_ + gbase + (size_t)q0 * HDIM;
        #pragma unroll
        for (int i = 0; i < 4; i++) {
            int c = tid + i * 256;
            int row = c >> 3, cc = c & 7;
            uint32_t off = swz128(row * 128 + cc * 16);
            cp_async16(QH + off, s0 + (size_t)row * HDIM + cc * 8);
            cp_async16(QL + off, s1 + (size_t)row * HDIM + cc * 8);
        }
    }
    auto load_kv = [&](int kt, int s) {
        const int k0 = kt * 64;
        const __half* srcs[2] = {kh_ + gbase + (size_t)k0 * HDIM, vh_ + gbase + (size_t)k0 * HDIM};
        #pragma unroll
        for (int t = 0; t < 2; t++) {
            uint32_t dstb = ST + s * 16384 + t * 8192;
            #pragma unroll
            for (int i = 0; i < 2; i++) {
                int c = tid + i * 256;
                int row = c >> 3, cc = c & 7;
                cp_async16(dstb + swz128(row * 128 + cc * 16), srcs[t] + (size_t)row * HDIM + cc * 8);
            }
        }
    };
    load_kv(0, 0);
    CP_COMMIT();

    float m0 = -INFINITY, m1 = -INFINITY, l0 = 0.f, l1 = 0.f;
    float oacc[8][4];
    #pragma unroll
    for (int nb = 0; nb < 8; nb++)
        #pragma unroll
        for (int j = 0; j < 4; j++) oacc[nb][j] = 0.f;

    const int r = lane >> 2, tig = lane & 3;
    const int a_row = wm * 16 + (lane & 7) + ((lane >> 3) & 1) * 8;
    const int a_colb = (lane >> 4) * 16;
    const int b_rowK = (lane & 7) + (lane >> 4) * 8;
    const int b_colbK = ((lane >> 3) & 1) * 16;
    const int v_row = (lane & 7) + ((lane >> 3) & 1) * 8;
    const int v_colb = (lane >> 4) * 16;

    const int nk = 2 * qt + 2;
    for (int kt = 0; kt < nk; kt++) {
        const int cur = kt & 1;
        if (kt + 1 < nk) { load_kv(kt + 1, cur ^ 1); CP_COMMIT(); CP_WAIT(1); }
        else             { CP_WAIT(0); }
        __syncthreads();
        const int k0 = kt * 64;
        const uint32_t KH = ST + cur * 16384, VH = KH + 8192;
        const bool active = (k0 <= q0 + wm * 16 + 15);
        if (active) {
            float sacc[8][4];
            #pragma unroll
            for (int nb = 0; nb < 8; nb++)
                #pragma unroll
                for (int j = 0; j < 4; j++) sacc[nb][j] = 0.f;
            #pragma unroll
            for (int ks = 0; ks < 4; ks++) {
                uint32_t ah[4], al[4];
                const uint32_t aoff = swz128(a_row * 128 + a_colb + ks * 32);
                ldsm_x4(ah, QH + aoff);
                ldsm_x4(al, QL + aoff);
                #pragma unroll
                for (int nb16 = 0; nb16 < 4; nb16++) {
                    uint32_t bh4[4];
                    const uint32_t boff = swz128((nb16 * 16 + b_rowK) * 128 + b_colbK + ks * 32);
                    ldsm_x4(bh4, KH + boff);
                    #pragma unroll
                    for (int h = 0; h < 2; h++) {
                        float* d = sacc[nb16 * 2 + h];
                        mma16816h(d, ah, &bh4[h * 2]);
                        mma16816h(d, al, &bh4[h * 2]);
                    }
                }
            }
            if (k0 + 63 > q0 + wm * 16) {
                #pragma unroll
                for (int nb = 0; nb < 8; nb++)
                    #pragma unroll
                    for (int j = 0; j < 4; j++) {
                        const int qrow = q0 + wm * 16 + r + (j >> 1) * 8;
                        const int kcol = k0 + nb * 8 + tig * 2 + (j & 1);
                        if (kcol > qrow) sacc[nb][j] = -INFINITY;
                    }
            }
            float rx0 = -INFINITY, rx1 = -INFINITY;
            #pragma unroll
            for (int nb = 0; nb < 8; nb++) {
                rx0 = fmaxf(rx0, fmaxf(sacc[nb][0], sacc[nb][1]));
                rx1 = fmaxf(rx1, fmaxf(sacc[nb][2], sacc[nb][3]));
            }
            #pragma unroll
            for (int off = 1; off <= 2; off <<= 1) {
                rx0 = fmaxf(rx0, __shfl_xor_sync(0xffffffffu, rx0, off));
                rx1 = fmaxf(rx1, __shfl_xor_sync(0xffffffffu, rx1, off));
            }
            const float nm0 = fmaxf(m0, rx0), nm1 = fmaxf(m1, rx1);
            const float sc0 = exp2f(m0 - nm0), sc1 = exp2f(m1 - nm1);
            float rs0 = 0.f, rs1 = 0.f;
            #pragma unroll
            for (int nb = 0; nb < 8; nb++) {
                sacc[nb][0] = exp2f(sacc[nb][0] - nm0);
                sacc[nb][1] = exp2f(sacc[nb][1] - nm0);
                sacc[nb][2] = exp2f(sacc[nb][2] - nm1);
                sacc[nb][3] = exp2f(sacc[nb][3] - nm1);
                rs0 += sacc[nb][0] + sacc[nb][1];
                rs1 += sacc[nb][2] + sacc[nb][3];
            }
            #pragma unroll
            for (int off = 1; off <= 2; off <<= 1) {
                rs0 += __shfl_xor_sync(0xffffffffu, rs0, off);
                rs1 += __shfl_xor_sync(0xffffffffu, rs1, off);
            }
            l0 = l0 * sc0 + rs0;
            l1 = l1 * sc1 + rs1;
            m0 = nm0; m1 = nm1;
            #pragma unroll
            for (int nb = 0; nb < 8; nb++) {
                oacc[nb][0] *= sc0; oacc[nb][1] *= sc0;
                oacc[nb][2] *= sc1; oacc[nb][3] *= sc1;
            }
            #pragma unroll
            for (int j = 0; j < 4; j++) {
                uint32_t pah[4], pal[4];
                split_pack_h(sacc[2 * j][0],     sacc[2 * j][1],     pah[0], pal[0]);
                split_pack_h(sacc[2 * j][2],     sacc[2 * j][3],     pah[1], pal[1]);
                split_pack_h(sacc[2 * j + 1][0], sacc[2 * j + 1][1], pah[2], pal[2]);
                split_pack_h(sacc[2 * j + 1][2], sacc[2 * j + 1][3], pah[3], pal[3]);
                #pragma unroll
                for (int nb16 = 0; nb16 < 4; nb16++) {
                    uint32_t vh4[4];
                    const uint32_t voff = swz128((16 * j + v_row) * 128 + nb16 * 32 + v_colb);
                    ldsm_x4_t(vh4, VH + voff);
                    #pragma unroll
                    for (int h = 0; h < 2; h++) {
                        float* d = oacc[nb16 * 2 + h];
                        mma16816h(d, pah, &vh4[h * 2]);
                        mma16816h(d, pal, &vh4[h * 2]);
                    }
                }
            }
        }
        __syncthreads();
    }

    const float inv0 = 1.0f / l0, inv1 = 1.0f / l1;
    const int b = bh >> 4, h = bh & 15;
    #pragma unroll
    for (int half = 0; half < 2; half++) {
        const int t = q0 + wm * 16 + r + half * 8;
        const float inv = half ? inv1 : inv0;
        const size_t off = ((size_t)(b * TSEQ + t)) * EMBED + h * HDIM;
        #pragma unroll
        for (int nb = 0; nb < 8; nb++) {
            const float v0 = oacc[nb][half * 2 + 0] * inv;
            const float v1 = oacc[nb][half * 2 + 1] * inv;
            *(uint32_t*)(Ohi + off + nb * 8 + tig * 2) = pack_h(v0, v1);
        }
    }
}

// ================= launch =================
extern "C" void kernel_launch(void* const* d_in, const int* in_sizes, int n_in,
                              void* d_out, int out_size)
{
    const float* x  = (const float*)d_in[0];
    const float* Wq = (const float*)d_in[1];
    const float* bq = (const float*)d_in[2];
    const float* Wk = (const float*)d_in[3];
    const float* bk = (const float*)d_in[4];
    const float* Wv = (const float*)d_in[5];
    const float* bv = (const float*)d_in[6];
    const float* Wp = (const float*)d_in[7];
    const float* bp = (const float*)d_in[8];
    float* out = (float*)d_out;

    __half *qh, *ql, *kh, *vh, *ohi, *xhi, *xlo, *wth;
    cudaGetSymbolAddress((void**)&qh, g_qh);
    cudaGetSymbolAddress((void**)&ql, g_ql);
    cudaGetSymbolAddress((void**)&kh, g_kh);
    cudaGetSymbolAddress((void**)&vh, g_vh);
    cudaGetSymbolAddress((void**)&ohi, g_ohi);
    cudaGetSymbolAddress((void**)&xhi, g_xhi);
    cudaGetSymbolAddress((void**)&xlo, g_xlo);
    cudaGetSymbolAddress((void**)&wth, g_wth);

    const int gemm_smem = 2 * STAGE_B;     // 98304
    const int ogemm_smem = 2 * OSTAGE_B;   // 65536
    cudaFuncSetAttribute(qkv_gemm, cudaFuncAttributeMaxDynamicSharedMemorySize, gemm_smem);
    cudaFuncSetAttribute(out_gemm, cudaFuncAttributeMaxDynamicSharedMemorySize, ogemm_smem);
    const int attn_smem = 65536;
    cudaFuncSetAttribute(attn_mma, cudaFuncAttributeMaxDynamicSharedMemorySize, attn_smem);

    const size_t WN = (size_t)EMBED * EMBED;

    split_f32<<<(MROWS * EMBED / 4 + 255) / 256, 256>>>(x, xhi, xlo, MROWS * EMBED / 4);
    dim3 tgrid(EMBED / 32, EMBED / 32, 4);
    dim3 tblk(32, 8);
    transpose_h4<<<tgrid, tblk>>>(Wq, Wk, Wv, Wp, wth);

    dim3 qkv_grid(24, MROWS / 128);   // (24, 64)
    qkv_gemm<<<qkv_grid, 256, gemm_smem>>>(xhi, xlo, wth, bq, bk, bv, qh, ql, kh, vh);

    dim3 agrid(TSEQ / 128, BATCH * HEADS);  // (16, 64)
    attn_mma<<<agrid, 256, attn_smem>>>(qh, ql, kh, vh, ohi);

    dim3 ogrid(EMBED / 128, MROWS / 128);   // (8, 64)
    out_gemm<<<ogrid, 256, ogemm_smem>>>(ohi, wth + 3 * WN, bp, out);

    (void)in_sizes; (void)n_in; (void)out_size;
}

// round 8
// speedup vs baseline: 9.0454x; 1.5430x over previous
#include <cuda_runtime.h>
#include <cuda_fp16.h>
#include <math.h>
#include <stdint.h>

#define EMBED   1024
#define HEADS   16
#define HDIM    64
#define BATCH   4
#define TSEQ    2048
#define MROWS   (BATCH * TSEQ)   // 8192

// ================= helpers =================
__device__ __forceinline__ uint32_t smem_u32(const void* p) {
    uint32_t a;
    asm("{ .reg .u64 t; cvta.to.shared.u64 t, %1; cvt.u32.u64 %0, t; }" : "=r"(a) : "l"(p));
    return a;
}
__device__ __forceinline__ uint32_t swz128(uint32_t off) { return off ^ ((off >> 3) & 0x70); }

__device__ __forceinline__ void cp_async16(uint32_t dst, const void* src) {
    asm volatile("cp.async.cg.shared.global [%0], [%1], 16;" :: "r"(dst), "l"(src));
}
#define CP_COMMIT() asm volatile("cp.async.commit_group;" ::: "memory")
#define CP_WAIT(n)  asm volatile("cp.async.wait_group %0;" :: "n"(n) : "memory")

__device__ __forceinline__ void ldsm_x4(uint32_t* r, uint32_t addr) {
    asm volatile("ldmatrix.sync.aligned.m8n8.x4.shared.b16 {%0,%1,%2,%3}, [%4];"
        : "=r"(r[0]), "=r"(r[1]), "=r"(r[2]), "=r"(r[3]) : "r"(addr));
}
__device__ __forceinline__ void ldsm_x4_t(uint32_t* r, uint32_t addr) {
    asm volatile("ldmatrix.sync.aligned.m8n8.x4.trans.shared.b16 {%0,%1,%2,%3}, [%4];"
        : "=r"(r[0]), "=r"(r[1]), "=r"(r[2]), "=r"(r[3]) : "r"(addr));
}
__device__ __forceinline__ void mma16816h(float* d, const uint32_t* a, const uint32_t* b) {
    asm volatile("mma.sync.aligned.m16n8k16.row.col.f32.f16.f16.f32 "
        "{%0,%1,%2,%3}, {%4,%5,%6,%7}, {%8,%9}, {%0,%1,%2,%3};"
        : "+f"(d[0]), "+f"(d[1]), "+f"(d[2]), "+f"(d[3])
        : "r"(a[0]), "r"(a[1]), "r"(a[2]), "r"(a[3]), "r"(b[0]), "r"(b[1]));
}
__device__ __forceinline__ uint32_t pack_h(float x, float y) {
    __half hx = __float2half_rn(x), hy = __float2half_rn(y);
    return (uint32_t)__half_as_ushort(hx) | ((uint32_t)__half_as_ushort(hy) << 16);
}

// ================= scratch (all single fp16) =================
__device__ __half g_qh[BATCH * HEADS * TSEQ * HDIM];
__device__ __half g_kh[BATCH * HEADS * TSEQ * HDIM];
__device__ __half g_vh[BATCH * HEADS * TSEQ * HDIM];
__device__ __half g_oh[MROWS * EMBED];
__device__ __half g_xh[MROWS * EMBED];
__device__ __half g_wth[4 * EMBED * EMBED];   // Wt[N,K] per weight

// softmax exp2 fold: Q scaled by 1/8 * log2(e)
#define QSCALE (0.125f * 1.4426950408889634f)

// ================= cast x -> fp16 =================
__global__ __launch_bounds__(256)
void cast_f32h(const float* __restrict__ in, __half* __restrict__ hi, int n4)
{
    int i = blockIdx.x * blockDim.x + threadIdx.x;
    if (i >= n4) return;
    float4 v = ((const float4*)in)[i];
    ((uint2*)hi)[i] = make_uint2(pack_h(v.x, v.y), pack_h(v.z, v.w));
}

// ================= transpose all 4 weights (z = weight idx) =================
__global__ __launch_bounds__(256)
void transpose_h4(const float* __restrict__ W0, const float* __restrict__ W1,
                  const float* __restrict__ W2, const float* __restrict__ W3,
                  __half* __restrict__ hi)
{
    __shared__ float t[32][33];
    const int z = blockIdx.z;
    const float* W = (z == 0) ? W0 : (z == 1) ? W1 : (z == 2) ? W2 : W3;
    __half* dst = hi + (size_t)z * EMBED * EMBED;
    const int bx = blockIdx.x * 32;   // N
    const int by = blockIdx.y * 32;   // K
    const int x = threadIdx.x, y = threadIdx.y;  // 32 x 8
    #pragma unroll
    for (int j = 0; j < 32; j += 8)
        t[y + j][x] = W[(size_t)(by + y + j) * EMBED + bx + x];
    __syncthreads();
    #pragma unroll
    for (int j = 0; j < 32; j += 8)
        dst[(size_t)(bx + y + j) * EMBED + by + x] = __float2half_rn(t[x][y + j]);
}

// ================= single-fp16 HMMA GEMM =================
#define TILE_B  16384     // 128 rows x 64 fp16 x 2B
#define STAGE_B 32768     // 2 tiles: Ah, Bh

// fused QKV: grid (24, 64). widx = bx>>3 selects weight/output.
__global__ __launch_bounds__(256, 2)
void qkv_gemm(const __half* __restrict__ Ah_, const __half* __restrict__ Wh,
              const float* __restrict__ bq, const float* __restrict__ bk, const float* __restrict__ bv,
              __half* __restrict__ qh, __half* __restrict__ kh, __half* __restrict__ vh)
{
    constexpr int K = EMBED, NK = 16;
    extern __shared__ __align__(1024) char smem[];
    const uint32_t sb = smem_u32(smem);
    const int tid = threadIdx.x, wid = tid >> 5, lane = tid & 31;
    const int widx = blockIdx.x >> 3;
    const int n0 = (blockIdx.x & 7) * 128, m0 = blockIdx.y * 128;
    const size_t WN = (size_t)EMBED * EMBED;

    const __half* Bh = Wh + (size_t)widx * WN;
    const float* bias = (widx == 0) ? bq : (widx == 1) ? bk : bv;
    __half* Cdst = (widx == 0) ? qh : (widx == 1) ? kh : vh;
    const float scale = (widx == 0) ? QSCALE : 1.0f;

    const int warp_m = wid & 3, warp_n = wid >> 2;
    float acc[2][8][4];
    #pragma unroll
    for (int mb = 0; mb < 2; mb++)
        #pragma unroll
        for (int nb = 0; nb < 8; nb++)
            #pragma unroll
            for (int j = 0; j < 4; j++) acc[mb][nb][j] = 0.f;

    const int a_row = warp_m * 32 + (lane & 7) + ((lane >> 3) & 1) * 8;
    const int a_col = (lane >> 4) * 16;
    const int b_row = warp_n * 64 + (lane & 7) + (lane >> 4) * 8;
    const int b_col = ((lane >> 3) & 1) * 16;

    const __half* srcs[2] = {Ah_, Bh};

    auto load_chunk = [&](int kt, int s) {
        #pragma unroll
        for (int t = 0; t < 2; t++) {
            const __half* base = srcs[t] + (size_t)((t == 0) ? m0 : n0) * K + kt * 64;
            const uint32_t tb = sb + s * STAGE_B + t * TILE_B;
            #pragma unroll
            for (int i = 0; i < 4; i++) {
                int chunk = tid + i * 256;
                int r = chunk >> 3, c = chunk & 7;
                cp_async16(tb + swz128(r * 128 + c * 16), base + (size_t)r * K + c * 8);
            }
        }
        CP_COMMIT();
    };

    load_chunk(0, 0);
    for (int kt = 0; kt < NK; kt++) {
        const int cur = kt & 1;
        if (kt + 1 < NK) { load_chunk(kt + 1, cur ^ 1); CP_WAIT(1); }
        else             { CP_WAIT(0); }
        __syncthreads();
        const uint32_t tAh = sb + cur * STAGE_B, tBh = tAh + TILE_B;
        #pragma unroll
        for (int ks = 0; ks < 4; ks++) {
            uint32_t ah[2][4], bh4[4][4];
            #pragma unroll
            for (int mb = 0; mb < 2; mb++)
                ldsm_x4(ah[mb], tAh + swz128((a_row + mb * 16) * 128 + a_col + ks * 32));
            #pragma unroll
            for (int nb = 0; nb < 4; nb++)
                ldsm_x4(bh4[nb], tBh + swz128((b_row + nb * 16) * 128 + b_col + ks * 32));
            #pragma unroll
            for (int mb = 0; mb < 2; mb++)
                #pragma unroll
                for (int nb = 0; nb < 4; nb++)
                    #pragma unroll
                    for (int h = 0; h < 2; h++)
                        mma16816h(acc[mb][nb * 2 + h], ah[mb], &bh4[nb][h * 2]);
        }
        __syncthreads();
    }

    const int er = m0 + warp_m * 32 + (lane >> 2);
    const int ec = n0 + warp_n * 64 + (lane & 3) * 2;
    #pragma unroll
    for (int mb = 0; mb < 2; mb++) {
        #pragma unroll
        for (int half = 0; half < 2; half++) {
            const int row = er + mb * 16 + half * 8;
            const int b = row / TSEQ, t = row % TSEQ;
            #pragma unroll
            for (int nb = 0; nb < 8; nb++) {
                const int col = ec + nb * 8;
                const float v0 = (acc[mb][nb][half * 2 + 0] + bias[col]) * scale;
                const float v1 = (acc[mb][nb][half * 2 + 1] + bias[col + 1]) * scale;
                const int hh = col >> 6, dd = col & 63;
                const size_t idx = (((size_t)(b * HEADS + hh)) * TSEQ + t) * HDIM + dd;
                *(uint32_t*)(Cdst + idx) = pack_h(v0, v1);
            }
        }
    }
}

// out-projection: f32 output [M,N]
__global__ __launch_bounds__(256, 2)
void out_gemm(const __half* __restrict__ Ah_, const __half* __restrict__ Bh_,
              const float* __restrict__ bias, float* __restrict__ Cf)
{
    constexpr int K = EMBED, NG = EMBED, NK = 16;
    extern __shared__ __align__(1024) char smem[];
    const uint32_t sb = smem_u32(smem);
    const int tid = threadIdx.x, wid = tid >> 5, lane = tid & 31;
    const int n0 = blockIdx.x * 128, m0 = blockIdx.y * 128;

    const int warp_m = wid & 3, warp_n = wid >> 2;
    float acc[2][8][4];
    #pragma unroll
    for (int mb = 0; mb < 2; mb++)
        #pragma unroll
        for (int nb = 0; nb < 8; nb++)
            #pragma unroll
            for (int j = 0; j < 4; j++) acc[mb][nb][j] = 0.f;

    const int a_row = warp_m * 32 + (lane & 7) + ((lane >> 3) & 1) * 8;
    const int a_col = (lane >> 4) * 16;
    const int b_row = warp_n * 64 + (lane & 7) + (lane >> 4) * 8;
    const int b_col = ((lane >> 3) & 1) * 16;

    const __half* srcs[2] = {Ah_, Bh_};

    auto load_chunk = [&](int kt, int s) {
        #pragma unroll
        for (int t = 0; t < 2; t++) {
            const __half* base = srcs[t] + (size_t)((t == 0) ? m0 : n0) * K + kt * 64;
            const uint32_t tb = sb + s * STAGE_B + t * TILE_B;
            #pragma unroll
            for (int i = 0; i < 4; i++) {
                int chunk = tid + i * 256;
                int r = chunk >> 3, c = chunk & 7;
                cp_async16(tb + swz128(r * 128 + c * 16), base + (size_t)r * K + c * 8);
            }
        }
        CP_COMMIT();
    };

    load_chunk(0, 0);
    for (int kt = 0; kt < NK; kt++) {
        const int cur = kt & 1;
        if (kt + 1 < NK) { load_chunk(kt + 1, cur ^ 1); CP_WAIT(1); }
        else             { CP_WAIT(0); }
        __syncthreads();
        const uint32_t tAh = sb + cur * STAGE_B, tBh = tAh + TILE_B;
        #pragma unroll
        for (int ks = 0; ks < 4; ks++) {
            uint32_t ah[2][4], bh4[4][4];
            #pragma unroll
            for (int mb = 0; mb < 2; mb++)
                ldsm_x4(ah[mb], tAh + swz128((a_row + mb * 16) * 128 + a_col + ks * 32));
            #pragma unroll
            for (int nb = 0; nb < 4; nb++)
                ldsm_x4(bh4[nb], tBh + swz128((b_row + nb * 16) * 128 + b_col + ks * 32));
            #pragma unroll
            for (int mb = 0; mb < 2; mb++)
                #pragma unroll
                for (int nb = 0; nb < 4; nb++)
                    #pragma unroll
                    for (int h = 0; h < 2; h++)
                        mma16816h(acc[mb][nb * 2 + h], ah[mb], &bh4[nb][h * 2]);
        }
        __syncthreads();
    }

    const int er = m0 + warp_m * 32 + (lane >> 2);
    const int ec = n0 + warp_n * 64 + (lane & 3) * 2;
    #pragma unroll
    for (int mb = 0; mb < 2; mb++) {
        #pragma unroll
        for (int half = 0; half < 2; half++) {
            const int row = er + mb * 16 + half * 8;
            #pragma unroll
            for (int nb = 0; nb < 8; nb++) {
                const int col = ec + nb * 8;
                float* dst = Cf + (size_t)row * NG + col;
                dst[0] = acc[mb][nb][half * 2 + 0] + bias[col];
                dst[1] = acc[mb][nb][half * 2 + 1] + bias[col + 1];
            }
        }
    }
}

// ================= single-fp16 HMMA causal flash attention =================
// smem: QH 16K | 2 stages x (KH 8K + VH 8K) = 48K total
__global__ __launch_bounds__(256, 2)
void attn_mma(const __half* __restrict__ qh_, const __half* __restrict__ kh_,
              const __half* __restrict__ vh_, __half* __restrict__ Oh)
{
    extern __shared__ __align__(1024) char smem[];
    const uint32_t sb = smem_u32(smem);
    const int qt = gridDim.x - 1 - blockIdx.x;   // longest tiles first
    const int bh = blockIdx.y;
    const int tid = threadIdx.x, wm = tid >> 5, lane = tid & 31;
    const int q0 = qt * 128;
    const size_t gbase = (size_t)bh * TSEQ * HDIM;

    const uint32_t QH = sb;
    const uint32_t ST = sb + 16384;

    {
        const __half* s0 = qh_ + gbase + (size_t)q0 * HDIM;
        #pragma unroll
        for (int i = 0; i < 4; i++) {
            int c = tid + i * 256;
            int row = c >> 3, cc = c & 7;
            cp_async16(QH + swz128(row * 128 + cc * 16), s0 + (size_t)row * HDIM + cc * 8);
        }
    }
    auto load_kv = [&](int kt, int s) {
        const int k0 = kt * 64;
        const __half* srcs[2] = {kh_ + gbase + (size_t)k0 * HDIM, vh_ + gbase + (size_t)k0 * HDIM};
        #pragma unroll
        for (int t = 0; t < 2; t++) {
            uint32_t dstb = ST + s * 16384 + t * 8192;
            #pragma unroll
            for (int i = 0; i < 2; i++) {
                int c = tid + i * 256;
                int row = c >> 3, cc = c & 7;
                cp_async16(dstb + swz128(row * 128 + cc * 16), srcs[t] + (size_t)row * HDIM + cc * 8);
            }
        }
    };
    load_kv(0, 0);
    CP_COMMIT();

    float m0 = -INFINITY, m1 = -INFINITY, l0 = 0.f, l1 = 0.f;
    float oacc[8][4];
    #pragma unroll
    for (int nb = 0; nb < 8; nb++)
        #pragma unroll
        for (int j = 0; j < 4; j++) oacc[nb][j] = 0.f;

    const int r = lane >> 2, tig = lane & 3;
    const int a_row = wm * 16 + (lane & 7) + ((lane >> 3) & 1) * 8;
    const int a_colb = (lane >> 4) * 16;
    const int b_rowK = (lane & 7) + (lane >> 4) * 8;
    const int b_colbK = ((lane >> 3) & 1) * 16;
    const int v_row = (lane & 7) + ((lane >> 3) & 1) * 8;
    const int v_colb = (lane >> 4) * 16;

    const int nk = 2 * qt + 2;
    for (int kt = 0; kt < nk; kt++) {
        const int cur = kt & 1;
        if (kt + 1 < nk) { load_kv(kt + 1, cur ^ 1); CP_COMMIT(); CP_WAIT(1); }
        else             { CP_WAIT(0); }
        __syncthreads();
        const int k0 = kt * 64;
        const uint32_t KH = ST + cur * 16384, VH = KH + 8192;
        const bool active = (k0 <= q0 + wm * 16 + 15);
        if (active) {
            float sacc[8][4];
            #pragma unroll
            for (int nb = 0; nb < 8; nb++)
                #pragma unroll
                for (int j = 0; j < 4; j++) sacc[nb][j] = 0.f;
            #pragma unroll
            for (int ks = 0; ks < 4; ks++) {
                uint32_t ah[4];
                ldsm_x4(ah, QH + swz128(a_row * 128 + a_colb + ks * 32));
                #pragma unroll
                for (int nb16 = 0; nb16 < 4; nb16++) {
                    uint32_t bh4[4];
                    ldsm_x4(bh4, KH + swz128((nb16 * 16 + b_rowK) * 128 + b_colbK + ks * 32));
                    #pragma unroll
                    for (int h = 0; h < 2; h++)
                        mma16816h(sacc[nb16 * 2 + h], ah, &bh4[h * 2]);
                }
            }
            if (k0 + 63 > q0 + wm * 16) {
                #pragma unroll
                for (int nb = 0; nb < 8; nb++)
                    #pragma unroll
                    for (int j = 0; j < 4; j++) {
                        const int qrow = q0 + wm * 16 + r + (j >> 1) * 8;
                        const int kcol = k0 + nb * 8 + tig * 2 + (j & 1);
                        if (kcol > qrow) sacc[nb][j] = -INFINITY;
                    }
            }
            float rx0 = -INFINITY, rx1 = -INFINITY;
            #pragma unroll
            for (int nb = 0; nb < 8; nb++) {
                rx0 = fmaxf(rx0, fmaxf(sacc[nb][0], sacc[nb][1]));
                rx1 = fmaxf(rx1, fmaxf(sacc[nb][2], sacc[nb][3]));
            }
            #pragma unroll
            for (int off = 1; off <= 2; off <<= 1) {
                rx0 = fmaxf(rx0, __shfl_xor_sync(0xffffffffu, rx0, off));
                rx1 = fmaxf(rx1, __shfl_xor_sync(0xffffffffu, rx1, off));
            }
            const float nm0 = fmaxf(m0, rx0), nm1 = fmaxf(m1, rx1);
            const float sc0 = exp2f(m0 - nm0), sc1 = exp2f(m1 - nm1);
            float rs0 = 0.f, rs1 = 0.f;
            #pragma unroll
            for (int nb = 0; nb < 8; nb++) {
                sacc[nb][0] = exp2f(sacc[nb][0] - nm0);
                sacc[nb][1] = exp2f(sacc[nb][1] - nm0);
                sacc[nb][2] = exp2f(sacc[nb][2] - nm1);
                sacc[nb][3] = exp2f(sacc[nb][3] - nm1);
                rs0 += sacc[nb][0] + sacc[nb][1];
                rs1 += sacc[nb][2] + sacc[nb][3];
            }
            #pragma unroll
            for (int off = 1; off <= 2; off <<= 1) {
                rs0 += __shfl_xor_sync(0xffffffffu, rs0, off);
                rs1 += __shfl_xor_sync(0xffffffffu, rs1, off);
            }
            l0 = l0 * sc0 + rs0;
            l1 = l1 * sc1 + rs1;
            m0 = nm0; m1 = nm1;
            #pragma unroll
            for (int nb = 0; nb < 8; nb++) {
                oacc[nb][0] *= sc0; oacc[nb][1] *= sc0;
                oacc[nb][2] *= sc1; oacc[nb][3] *= sc1;
            }
            #pragma unroll
            for (int j = 0; j < 4; j++) {
                uint32_t pah[4];
                pah[0] = pack_h(sacc[2 * j][0],     sacc[2 * j][1]);
                pah[1] = pack_h(sacc[2 * j][2],     sacc[2 * j][3]);
                pah[2] = pack_h(sacc[2 * j + 1][0], sacc[2 * j + 1][1]);
                pah[3] = pack_h(sacc[2 * j + 1][2], sacc[2 * j + 1][3]);
                #pragma unroll
                for (int nb16 = 0; nb16 < 4; nb16++) {
                    uint32_t vh4[4];
                    ldsm_x4_t(vh4, VH + swz128((16 * j + v_row) * 128 + nb16 * 32 + v_colb));
                    #pragma unroll
                    for (int h = 0; h < 2; h++)
                        mma16816h(oacc[nb16 * 2 + h], pah, &vh4[h * 2]);
                }
            }
        }
        __syncthreads();
    }

    const float inv0 = 1.0f / l0, inv1 = 1.0f / l1;
    const int b = bh >> 4, h = bh & 15;
    #pragma unroll
    for (int half = 0; half < 2; half++) {
        const int t = q0 + wm * 16 + r + half * 8;
        const float inv = half ? inv1 : inv0;
        const size_t off = ((size_t)(b * TSEQ + t)) * EMBED + h * HDIM;
        #pragma unroll
        for (int nb = 0; nb < 8; nb++) {
            const float v0 = oacc[nb][half * 2 + 0] * inv;
            const float v1 = oacc[nb][half * 2 + 1] * inv;
            *(uint32_t*)(Oh + off + nb * 8 + tig * 2) = pack_h(v0, v1);
        }
    }
}

// ================= launch =================
extern "C" void kernel_launch(void* const* d_in, const int* in_sizes, int n_in,
                              void* d_out, int out_size)
{
    const float* x  = (const float*)d_in[0];
    const float* Wq = (const float*)d_in[1];
    const float* bq = (const float*)d_in[2];
    const float* Wk = (const float*)d_in[3];
    const float* bk = (const float*)d_in[4];
    const float* Wv = (const float*)d_in[5];
    const float* bv = (const float*)d_in[6];
    const float* Wp = (const float*)d_in[7];
    const float* bp = (const float*)d_in[8];
    float* out = (float*)d_out;

    __half *qh, *kh, *vh, *oh, *xh, *wth;
    cudaGetSymbolAddress((void**)&qh, g_qh);
    cudaGetSymbolAddress((void**)&kh, g_kh);
    cudaGetSymbolAddress((void**)&vh, g_vh);
    cudaGetSymbolAddress((void**)&oh, g_oh);
    cudaGetSymbolAddress((void**)&xh, g_xh);
    cudaGetSymbolAddress((void**)&wth, g_wth);

    const int gemm_smem = 2 * STAGE_B;   // 65536
    cudaFuncSetAttribute(qkv_gemm, cudaFuncAttributeMaxDynamicSharedMemorySize, gemm_smem);
    cudaFuncSetAttribute(out_gemm, cudaFuncAttributeMaxDynamicSharedMemorySize, gemm_smem);
    const int attn_smem = 16384 + 2 * 16384;   // 49152
    cudaFuncSetAttribute(attn_mma, cudaFuncAttributeMaxDynamicSharedMemorySize, attn_smem);

    const size_t WN = (size_t)EMBED * EMBED;

    cast_f32h<<<(MROWS * EMBED / 4 + 255) / 256, 256>>>(x, xh, MROWS * EMBED / 4);
    dim3 tgrid(EMBED / 32, EMBED / 32, 4);
    dim3 tblk(32, 8);
    transpose_h4<<<tgrid, tblk>>>(Wq, Wk, Wv, Wp, wth);

    dim3 qkv_grid(24, MROWS / 128);   // (24, 64)
    qkv_gemm<<<qkv_grid, 256, gemm_smem>>>(xh, wth, bq, bk, bv, qh, kh, vh);

    dim3 agrid(TSEQ / 128, BATCH * HEADS);  // (16, 64)
    attn_mma<<<agrid, 256, attn_smem>>>(qh, kh, vh, oh);

    dim3 ogrid(EMBED / 128, MROWS / 128);   // (8, 64)
    out_gemm<<<ogrid, 256, gemm_smem>>>(oh, wth + 3 * WN, bp, out);

    (void)in_sizes; (void)n_in; (void)out_size;
}